// round 1
// baseline (speedup 1.0000x reference)
#include <cuda_runtime.h>

#define B_  2
#define S_  2048
#define U_  1024
#define H_  16
#define DK_ 64

// scratch (allocation-free rule: __device__ globals)
__device__ float g_q[B_ * S_ * U_];
__device__ float g_k[B_ * S_ * U_];
__device__ float g_v[B_ * S_ * U_];
__device__ float g_att[B_ * S_ * U_];

// ---------------------------------------------------------------------------
// 128x128x8 fp32 GEMM body:  C[M,N] = A[M,K] @ W[N,K]^T + bias,  K=N=U_=1024
// 256 threads, each computes an 8x8 microtile.
// ---------------------------------------------------------------------------
__device__ __forceinline__ void gemm_body(const float* __restrict__ A,
                                          const float* __restrict__ W,
                                          const float* __restrict__ bias,
                                          float* __restrict__ C) {
    __shared__ float As[8][128];
    __shared__ float Ws[8][128];
    const int tid  = threadIdx.x;
    const int tx   = tid & 15;
    const int ty   = tid >> 4;
    const int bm   = blockIdx.y * 128;
    const int bn   = blockIdx.x * 128;
    const int lrow = tid >> 1;          // 0..127
    const int lk   = (tid & 1) * 4;     // 0 or 4

    const float* Ap = A + (size_t)(bm + lrow) * U_ + lk;
    const float* Wp = W + (size_t)(bn + lrow) * U_ + lk;

    float acc[8][8];
#pragma unroll
    for (int i = 0; i < 8; i++)
#pragma unroll
        for (int j = 0; j < 8; j++) acc[i][j] = 0.0f;

    for (int k0 = 0; k0 < U_; k0 += 8) {
        float4 a4 = *(const float4*)(Ap + k0);
        float4 w4 = *(const float4*)(Wp + k0);
        As[lk + 0][lrow] = a4.x; As[lk + 1][lrow] = a4.y;
        As[lk + 2][lrow] = a4.z; As[lk + 3][lrow] = a4.w;
        Ws[lk + 0][lrow] = w4.x; Ws[lk + 1][lrow] = w4.y;
        Ws[lk + 2][lrow] = w4.z; Ws[lk + 3][lrow] = w4.w;
        __syncthreads();
#pragma unroll
        for (int kk = 0; kk < 8; kk++) {
            float a[8], w[8];
            *(float4*)&a[0] = *(const float4*)&As[kk][ty * 8];
            *(float4*)&a[4] = *(const float4*)&As[kk][ty * 8 + 4];
            *(float4*)&w[0] = *(const float4*)&Ws[kk][tx * 8];
            *(float4*)&w[4] = *(const float4*)&Ws[kk][tx * 8 + 4];
#pragma unroll
            for (int i = 0; i < 8; i++)
#pragma unroll
                for (int j = 0; j < 8; j++)
                    acc[i][j] = fmaf(a[i], w[j], acc[i][j]);
        }
        __syncthreads();
    }

#pragma unroll
    for (int i = 0; i < 8; i++) {
        float* Cp = C + (size_t)(bm + ty * 8 + i) * U_ + bn;
#pragma unroll
        for (int j = 0; j < 8; j += 4) {
            float4 o;
            o.x = acc[i][j + 0] + bias[bn + tx * 8 + j + 0];
            o.y = acc[i][j + 1] + bias[bn + tx * 8 + j + 1];
            o.z = acc[i][j + 2] + bias[bn + tx * 8 + j + 2];
            o.w = acc[i][j + 3] + bias[bn + tx * 8 + j + 3];
            *(float4*)(Cp + tx * 8 + j) = o;
        }
    }
}

// Fused QKV projection: blockIdx.z selects which of the three GEMMs.
__global__ __launch_bounds__(256) void gemm_qkv(
    const float* __restrict__ Xq, const float* __restrict__ Xk, const float* __restrict__ Xv,
    const float* __restrict__ Wq, const float* __restrict__ Wk, const float* __restrict__ Wv,
    const float* __restrict__ bq, const float* __restrict__ bk, const float* __restrict__ bv) {
    const float* A; const float* W; const float* bias; float* C;
    if (blockIdx.z == 0)      { A = Xq; W = Wq; bias = bq; C = g_q; }
    else if (blockIdx.z == 1) { A = Xk; W = Wk; bias = bk; C = g_k; }
    else                      { A = Xv; W = Wv; bias = bv; C = g_v; }
    gemm_body(A, W, bias, C);
}

// Output projection: out = g_att @ Wo^T + bo
__global__ __launch_bounds__(256) void gemm_out(const float* __restrict__ Wo,
                                                const float* __restrict__ bo,
                                                float* __restrict__ out) {
    gemm_body(g_att, Wo, bo, out);
}

// ---------------------------------------------------------------------------
// Flash attention, fp32, causal. One CTA per (qtile=64 rows, head, batch).
// 64x64 kv tiles; thread layout 16x16, each thread owns a 4x4 of S and of O.
// Qs, Ks stored transposed [dk][pos] so the S-gemm inner loop is LDS.128.
// ---------------------------------------------------------------------------
#define FA_STRIDE 68
#define FA_SMEM   (4 * 64 * FA_STRIDE * 4)

__global__ __launch_bounds__(256) void flash_attn_kernel() {
    extern __shared__ float sm[];
    float* Qs = sm;                       // [dk=64][r=64]  (transposed), stride 68
    float* Ks = Qs + 64 * FA_STRIDE;      // [dk=64][c=64]  (transposed)
    float* Vs = Ks + 64 * FA_STRIDE;      // [kv=64][dk=64] (natural)
    float* Ps = Vs + 64 * FA_STRIDE;      // [r=64][kv=64]  (natural)

    const int tid = threadIdx.x;
    const int tx  = tid & 15;
    const int ty  = tid >> 4;
    const int qt  = (int)gridDim.x - 1 - (int)blockIdx.x;  // big tiles first
    const int h   = blockIdx.y;
    const int b   = blockIdx.z;
    const int qbase = qt * 64;

    const float* Qg = g_q + ((size_t)b * S_ + qbase) * U_ + h * DK_;
    const float* Kg = g_k + (size_t)b * S_ * U_ + h * DK_;
    const float* Vg = g_v + (size_t)b * S_ * U_ + h * DK_;

    const int c4 = (tid & 15) * 4;
    // load Q transposed, pre-scaled by 1/sqrt(DK) = 0.125
#pragma unroll
    for (int it = 0; it < 4; it++) {
        int r = (tid >> 4) + it * 16;
        float4 v = *(const float4*)(Qg + (size_t)r * U_ + c4);
        Qs[(c4 + 0) * FA_STRIDE + r] = v.x * 0.125f;
        Qs[(c4 + 1) * FA_STRIDE + r] = v.y * 0.125f;
        Qs[(c4 + 2) * FA_STRIDE + r] = v.z * 0.125f;
        Qs[(c4 + 3) * FA_STRIDE + r] = v.w * 0.125f;
    }

    float m_i[4], l_i[4], o_acc[4][4];
#pragma unroll
    for (int i = 0; i < 4; i++) {
        m_i[i] = -1e30f;
        l_i[i] = 0.0f;
#pragma unroll
        for (int j = 0; j < 4; j++) o_acc[i][j] = 0.0f;
    }

    for (int jt = 0; jt <= qt; jt++) {
        const int kbase = jt * 64;
        __syncthreads();   // previous PV done before overwriting Ks/Vs
        // load K (transposed) and V (natural)
#pragma unroll
        for (int it = 0; it < 4; it++) {
            int r = (tid >> 4) + it * 16;          // kv index in tile
            float4 kv4 = *(const float4*)(Kg + (size_t)(kbase + r) * U_ + c4);
            Ks[(c4 + 0) * FA_STRIDE + r] = kv4.x;
            Ks[(c4 + 1) * FA_STRIDE + r] = kv4.y;
            Ks[(c4 + 2) * FA_STRIDE + r] = kv4.z;
            Ks[(c4 + 3) * FA_STRIDE + r] = kv4.w;
            float4 vv4 = *(const float4*)(Vg + (size_t)(kbase + r) * U_ + c4);
            *(float4*)&Vs[r * FA_STRIDE + c4] = vv4;
        }
        __syncthreads();

        // S = Q K^T  (4x4 per thread)
        float s[4][4];
#pragma unroll
        for (int i = 0; i < 4; i++)
#pragma unroll
            for (int j = 0; j < 4; j++) s[i][j] = 0.0f;
#pragma unroll 8
        for (int k = 0; k < 64; k++) {
            float4 a = *(const float4*)&Qs[k * FA_STRIDE + ty * 4];
            float4 bb = *(const float4*)&Ks[k * FA_STRIDE + tx * 4];
            float av[4] = {a.x, a.y, a.z, a.w};
            float bv[4] = {bb.x, bb.y, bb.z, bb.w};
#pragma unroll
            for (int i = 0; i < 4; i++)
#pragma unroll
                for (int j = 0; j < 4; j++)
                    s[i][j] = fmaf(av[i], bv[j], s[i][j]);
        }

        if (jt == qt) {  // diagonal tile: causal mask within the tile
#pragma unroll
            for (int i = 0; i < 4; i++)
#pragma unroll
                for (int j = 0; j < 4; j++)
                    if (tx * 4 + j > ty * 4 + i) s[i][j] = -1e9f;
        }

        // online softmax per row (rows live across the 16 tx lanes)
#pragma unroll
        for (int i = 0; i < 4; i++) {
            float rm = fmaxf(fmaxf(s[i][0], s[i][1]), fmaxf(s[i][2], s[i][3]));
            rm = fmaxf(rm, __shfl_xor_sync(0xffffffffu, rm, 1));
            rm = fmaxf(rm, __shfl_xor_sync(0xffffffffu, rm, 2));
            rm = fmaxf(rm, __shfl_xor_sync(0xffffffffu, rm, 4));
            rm = fmaxf(rm, __shfl_xor_sync(0xffffffffu, rm, 8));
            float mn = fmaxf(m_i[i], rm);
            float corr = __expf(m_i[i] - mn);
            m_i[i] = mn;
            float rs = 0.0f;
#pragma unroll
            for (int j = 0; j < 4; j++) {
                float p = __expf(s[i][j] - mn);
                s[i][j] = p;
                rs += p;
            }
            rs += __shfl_xor_sync(0xffffffffu, rs, 1);
            rs += __shfl_xor_sync(0xffffffffu, rs, 2);
            rs += __shfl_xor_sync(0xffffffffu, rs, 4);
            rs += __shfl_xor_sync(0xffffffffu, rs, 8);
            l_i[i] = l_i[i] * corr + rs;
#pragma unroll
            for (int j = 0; j < 4; j++) o_acc[i][j] *= corr;
        }

        // stage P to smem (natural layout, vector stores)
#pragma unroll
        for (int i = 0; i < 4; i++) {
            float4 p4 = make_float4(s[i][0], s[i][1], s[i][2], s[i][3]);
            *(float4*)&Ps[(ty * 4 + i) * FA_STRIDE + tx * 4] = p4;
        }
        __syncthreads();

        // O += P @ V
#pragma unroll 8
        for (int k = 0; k < 64; k++) {
            float4 vv = *(const float4*)&Vs[k * FA_STRIDE + tx * 4];
            float vb[4] = {vv.x, vv.y, vv.z, vv.w};
            float p0 = Ps[(ty * 4 + 0) * FA_STRIDE + k];
            float p1 = Ps[(ty * 4 + 1) * FA_STRIDE + k];
            float p2 = Ps[(ty * 4 + 2) * FA_STRIDE + k];
            float p3 = Ps[(ty * 4 + 3) * FA_STRIDE + k];
#pragma unroll
            for (int j = 0; j < 4; j++) {
                o_acc[0][j] = fmaf(p0, vb[j], o_acc[0][j]);
                o_acc[1][j] = fmaf(p1, vb[j], o_acc[1][j]);
                o_acc[2][j] = fmaf(p2, vb[j], o_acc[2][j]);
                o_acc[3][j] = fmaf(p3, vb[j], o_acc[3][j]);
            }
        }
    }

    // epilogue: normalize and write back in [B,S,U] layout (head-major columns)
    float* Og = g_att + ((size_t)b * S_ + qbase) * U_ + h * DK_;
#pragma unroll
    for (int i = 0; i < 4; i++) {
        float inv = 1.0f / l_i[i];
        float4 o = make_float4(o_acc[i][0] * inv, o_acc[i][1] * inv,
                               o_acc[i][2] * inv, o_acc[i][3] * inv);
        *(float4*)(Og + (size_t)(ty * 4 + i) * U_ + tx * 4) = o;
    }
}

// ---------------------------------------------------------------------------
extern "C" void kernel_launch(void* const* d_in, const int* in_sizes, int n_in,
                              void* d_out, int out_size) {
    const float* query = (const float*)d_in[0];
    const float* key   = (const float*)d_in[1];
    const float* value = (const float*)d_in[2];
    // d_in[3] = mask (causal tril; applied analytically in the kernel)
    const float* Wq = (const float*)d_in[4];
    const float* bq = (const float*)d_in[5];
    const float* Wk = (const float*)d_in[6];
    const float* bk = (const float*)d_in[7];
    const float* Wv = (const float*)d_in[8];
    const float* bv = (const float*)d_in[9];
    const float* Wo = (const float*)d_in[10];
    const float* bo = (const float*)d_in[11];
    float* out = (float*)d_out;

    dim3 gq(U_ / 128, (B_ * S_) / 128, 3);
    gemm_qkv<<<gq, 256>>>(query, key, value, Wq, Wk, Wv, bq, bk, bv);

    cudaFuncSetAttribute(flash_attn_kernel,
                         cudaFuncAttributeMaxDynamicSharedMemorySize, FA_SMEM);
    dim3 ga(S_ / 64, H_, B_);
    flash_attn_kernel<<<ga, 256, FA_SMEM>>>();

    dim3 go(U_ / 128, (B_ * S_) / 128, 1);
    gemm_out<<<go, 256>>>(Wo, bo, out);
}

// round 3
// speedup vs baseline: 1.3782x; 1.3782x over previous
#include <cuda_runtime.h>
#include <cuda_bf16.h>
#include <cstdint>

#define B_  2
#define S_  2048
#define U_  1024
#define H_  16
#define DK_ 64

// scratch (allocation-free rule: __device__ globals)
__device__ float g_q[B_ * S_ * U_];
__device__ float g_k[B_ * S_ * U_];
__device__ float g_v[B_ * S_ * U_];
__device__ float g_att[B_ * S_ * U_];

// ---------------------------------------------------------------------------
// helpers
// ---------------------------------------------------------------------------
__device__ __forceinline__ uint32_t smem_u32(const void* p) {
    uint32_t a;
    asm("{ .reg .u64 t; cvta.to.shared.u64 t, %1; cvt.u32.u64 %0, t; }" : "=r"(a) : "l"(p));
    return a;
}

#define LDSM_X4(r0, r1, r2, r3, addr)                                         \
    asm volatile("ldmatrix.sync.aligned.m8n8.x4.shared.b16 {%0,%1,%2,%3}, [%4];" \
        : "=r"(r0), "=r"(r1), "=r"(r2), "=r"(r3) : "r"(addr))

#define MMA_BF16(d, a, b0, b1)                                                \
    asm volatile("mma.sync.aligned.m16n8k16.row.col.f32.bf16.bf16.f32 "       \
        "{%0,%1,%2,%3},{%4,%5,%6,%7},{%8,%9},{%0,%1,%2,%3};"                  \
        : "+f"((d)[0]), "+f"((d)[1]), "+f"((d)[2]), "+f"((d)[3])              \
        : "r"((a)[0]), "r"((a)[1]), "r"((a)[2]), "r"((a)[3]), "r"(b0), "r"(b1))

__device__ __forceinline__ uint32_t pack_bf16(__nv_bfloat16 a, __nv_bfloat16 b) {
    uint32_t ua = *reinterpret_cast<unsigned short*>(&a);
    uint32_t ub = *reinterpret_cast<unsigned short*>(&b);
    return ua | (ub << 16);
}

// split f into (hi, lo) bf16 pairs packed for a float4
__device__ __forceinline__ void cvt_split(const float4& f, uint2& hi, uint2& lo) {
    __nv_bfloat16 h0 = __float2bfloat16(f.x);
    __nv_bfloat16 h1 = __float2bfloat16(f.y);
    __nv_bfloat16 h2 = __float2bfloat16(f.z);
    __nv_bfloat16 h3 = __float2bfloat16(f.w);
    __nv_bfloat16 l0 = __float2bfloat16(f.x - __bfloat162float(h0));
    __nv_bfloat16 l1 = __float2bfloat16(f.y - __bfloat162float(h1));
    __nv_bfloat16 l2 = __float2bfloat16(f.z - __bfloat162float(h2));
    __nv_bfloat16 l3 = __float2bfloat16(f.w - __bfloat162float(h3));
    hi.x = pack_bf16(h0, h1); hi.y = pack_bf16(h2, h3);
    lo.x = pack_bf16(l0, l1); lo.y = pack_bf16(l2, l3);
}

// ---------------------------------------------------------------------------
// split-bf16 mma.sync GEMM: C[M,N] = A[M,K] @ W[N,K]^T + bias
// CTA 128x128, 8 warps (2x4), warp tile 64x32, K-chunk 32, 2-stage smem.
// ---------------------------------------------------------------------------
#define KC     32
#define NKC    (U_ / KC)            // 32 chunks
#define ROWB   80                   // 64B data + 16B pad (conflict-free ldmatrix)
#define TILE_B (128 * ROWB)         // 10240
#define ST_ALO (1 * TILE_B)
#define ST_WHI (2 * TILE_B)
#define ST_WLO (3 * TILE_B)
#define STAGE_B (4 * TILE_B)        // 40960
#define GT_SMEM (2 * STAGE_B)       // 81920

__device__ void gemm_mma_body(const float* __restrict__ A, const float* __restrict__ W,
                              const float* __restrict__ bias, float* __restrict__ C) {
    extern __shared__ char smem[];
    const int tid  = threadIdx.x;
    const int lane = tid & 31;
    const int wid  = tid >> 5;
    const int wm   = wid >> 2;          // 0..1
    const int wn   = wid & 3;           // 0..3
    const int bm   = blockIdx.y * 128;
    const int bn   = blockIdx.x * 128;

    // LDG mapping: thread covers row lr, 16 cols starting at lh*16
    const int lr = tid >> 1;
    const int lh = tid & 1;
    const float* Ag = A + (size_t)(bm + lr) * U_ + lh * 16;
    const float* Wg = W + (size_t)(bn + lr) * U_ + lh * 16;

    float4 bA[4], bW[4];
#pragma unroll
    for (int q = 0; q < 4; q++) {
        bA[q] = *(const float4*)(Ag + q * 4);
        bW[q] = *(const float4*)(Wg + q * 4);
    }

    float acc[4][4][4];
#pragma unroll
    for (int mf = 0; mf < 4; mf++)
#pragma unroll
        for (int nf = 0; nf < 4; nf++)
#pragma unroll
            for (int r = 0; r < 4; r++) acc[mf][nf][r] = 0.0f;

    const uint32_t sbase  = smem_u32(smem);
    const uint32_t a_row  = (uint32_t)(lane & 15);
    const uint32_t a_colh = (uint32_t)(((lane >> 4) & 1) * 16);
    const uint32_t b_nl   = (uint32_t)((lane & 7) + ((lane >> 4) & 1) * 8);
    const uint32_t b_ks   = (uint32_t)(((lane >> 3) & 1) * 16);

    const uint32_t sts_off = (uint32_t)(lr * ROWB + lh * 32);

    for (int c = 0; c < NKC; c++) {
        char* stp = smem + (size_t)(c & 1) * STAGE_B;
        // convert + STS (hi/lo for A and W)
#pragma unroll
        for (int q = 0; q < 4; q++) {
            uint2 hi, lo;
            cvt_split(bA[q], hi, lo);
            *(uint2*)(stp + sts_off + q * 8)          = hi;
            *(uint2*)(stp + ST_ALO + sts_off + q * 8) = lo;
            cvt_split(bW[q], hi, lo);
            *(uint2*)(stp + ST_WHI + sts_off + q * 8) = hi;
            *(uint2*)(stp + ST_WLO + sts_off + q * 8) = lo;
        }
        __syncthreads();
        if (c + 1 < NKC) {
#pragma unroll
            for (int q = 0; q < 4; q++) {
                bA[q] = *(const float4*)(Ag + (c + 1) * KC + q * 4);
                bW[q] = *(const float4*)(Wg + (c + 1) * KC + q * 4);
            }
        }
        const uint32_t st = sbase + (uint32_t)(c & 1) * STAGE_B;
#pragma unroll
        for (int ko = 0; ko < 2; ko++) {
            uint32_t ah[4][4], al[4][4];
#pragma unroll
            for (int mf = 0; mf < 4; mf++) {
                uint32_t ad = st + (uint32_t)((wm * 64 + mf * 16 + a_row) * ROWB)
                                 + (uint32_t)(ko * 32) + a_colh;
                LDSM_X4(ah[mf][0], ah[mf][1], ah[mf][2], ah[mf][3], ad);
                LDSM_X4(al[mf][0], al[mf][1], al[mf][2], al[mf][3], ad + ST_ALO);
            }
            uint32_t bh[2][4], bl[2][4];
#pragma unroll
            for (int np = 0; np < 2; np++) {
                uint32_t bd = st + ST_WHI
                            + (uint32_t)((wn * 32 + np * 16 + b_nl) * ROWB)
                            + (uint32_t)(ko * 32) + b_ks;
                LDSM_X4(bh[np][0], bh[np][1], bh[np][2], bh[np][3], bd);
                LDSM_X4(bl[np][0], bl[np][1], bl[np][2], bl[np][3], bd + TILE_B);
            }
#pragma unroll
            for (int mf = 0; mf < 4; mf++)
#pragma unroll
                for (int nf = 0; nf < 4; nf++) {
                    const uint32_t* bhp = &bh[nf >> 1][(nf & 1) * 2];
                    const uint32_t* blp = &bl[nf >> 1][(nf & 1) * 2];
                    MMA_BF16(acc[mf][nf], ah[mf], bhp[0], bhp[1]);  // hi*hi
                    MMA_BF16(acc[mf][nf], ah[mf], blp[0], blp[1]);  // hi*lo
                    MMA_BF16(acc[mf][nf], al[mf], bhp[0], bhp[1]);  // lo*hi
                }
        }
        __syncthreads();
    }

    // epilogue: fp32 accumulators + bias -> C
    const int tr = lane >> 2;
    const int tc = (lane & 3) * 2;
#pragma unroll
    for (int mf = 0; mf < 4; mf++) {
#pragma unroll
        for (int nf = 0; nf < 4; nf++) {
            int gr = bm + wm * 64 + mf * 16 + tr;
            int gc = bn + wn * 32 + nf * 8 + tc;
            float2 bv = *(const float2*)(bias + gc);
            float2 o0 = make_float2(acc[mf][nf][0] + bv.x, acc[mf][nf][1] + bv.y);
            float2 o1 = make_float2(acc[mf][nf][2] + bv.x, acc[mf][nf][3] + bv.y);
            *(float2*)(C + (size_t)gr * U_ + gc)       = o0;
            *(float2*)(C + (size_t)(gr + 8) * U_ + gc) = o1;
        }
    }
}

__global__ __launch_bounds__(256, 1) void gemm_mma_qkv(
    const float* __restrict__ Xq, const float* __restrict__ Xk, const float* __restrict__ Xv,
    const float* __restrict__ Wq, const float* __restrict__ Wk, const float* __restrict__ Wv,
    const float* __restrict__ bq, const float* __restrict__ bk, const float* __restrict__ bv) {
    const float* A; const float* W; const float* bias; float* C;
    if (blockIdx.z == 0)      { A = Xq; W = Wq; bias = bq; C = g_q; }
    else if (blockIdx.z == 1) { A = Xk; W = Wk; bias = bk; C = g_k; }
    else                      { A = Xv; W = Wv; bias = bv; C = g_v; }
    gemm_mma_body(A, W, bias, C);
}

__global__ __launch_bounds__(256, 1) void gemm_mma_out(const float* __restrict__ Wo,
                                                       const float* __restrict__ bo,
                                                       float* __restrict__ out) {
    gemm_mma_body(g_att, Wo, bo, out);
}

// ---------------------------------------------------------------------------
// Flash attention, fp32, causal (round-1 passing version, unchanged).
// ---------------------------------------------------------------------------
#define FA_STRIDE 68
#define FA_SMEM   (4 * 64 * FA_STRIDE * 4)

__global__ __launch_bounds__(256) void flash_attn_kernel() {
    extern __shared__ float sm[];
    float* Qs = sm;
    float* Ks = Qs + 64 * FA_STRIDE;
    float* Vs = Ks + 64 * FA_STRIDE;
    float* Ps = Vs + 64 * FA_STRIDE;

    const int tid = threadIdx.x;
    const int tx  = tid & 15;
    const int ty  = tid >> 4;
    const int qt  = (int)gridDim.x - 1 - (int)blockIdx.x;
    const int h   = blockIdx.y;
    const int b   = blockIdx.z;
    const int qbase = qt * 64;

    const float* Qg = g_q + ((size_t)b * S_ + qbase) * U_ + h * DK_;
    const float* Kg = g_k + (size_t)b * S_ * U_ + h * DK_;
    const float* Vg = g_v + (size_t)b * S_ * U_ + h * DK_;

    const int c4 = (tid & 15) * 4;
#pragma unroll
    for (int it = 0; it < 4; it++) {
        int r = (tid >> 4) + it * 16;
        float4 v = *(const float4*)(Qg + (size_t)r * U_ + c4);
        Qs[(c4 + 0) * FA_STRIDE + r] = v.x * 0.125f;
        Qs[(c4 + 1) * FA_STRIDE + r] = v.y * 0.125f;
        Qs[(c4 + 2) * FA_STRIDE + r] = v.z * 0.125f;
        Qs[(c4 + 3) * FA_STRIDE + r] = v.w * 0.125f;
    }

    float m_i[4], l_i[4], o_acc[4][4];
#pragma unroll
    for (int i = 0; i < 4; i++) {
        m_i[i] = -1e30f; l_i[i] = 0.0f;
#pragma unroll
        for (int j = 0; j < 4; j++) o_acc[i][j] = 0.0f;
    }

    for (int jt = 0; jt <= qt; jt++) {
        const int kbase = jt * 64;
        __syncthreads();
#pragma unroll
        for (int it = 0; it < 4; it++) {
            int r = (tid >> 4) + it * 16;
            float4 kv4 = *(const float4*)(Kg + (size_t)(kbase + r) * U_ + c4);
            Ks[(c4 + 0) * FA_STRIDE + r] = kv4.x;
            Ks[(c4 + 1) * FA_STRIDE + r] = kv4.y;
            Ks[(c4 + 2) * FA_STRIDE + r] = kv4.z;
            Ks[(c4 + 3) * FA_STRIDE + r] = kv4.w;
            float4 vv4 = *(const float4*)(Vg + (size_t)(kbase + r) * U_ + c4);
            *(float4*)&Vs[r * FA_STRIDE + c4] = vv4;
        }
        __syncthreads();

        float s[4][4];
#pragma unroll
        for (int i = 0; i < 4; i++)
#pragma unroll
            for (int j = 0; j < 4; j++) s[i][j] = 0.0f;
#pragma unroll 8
        for (int k = 0; k < 64; k++) {
            float4 a = *(const float4*)&Qs[k * FA_STRIDE + ty * 4];
            float4 bb = *(const float4*)&Ks[k * FA_STRIDE + tx * 4];
            float av[4] = {a.x, a.y, a.z, a.w};
            float bv[4] = {bb.x, bb.y, bb.z, bb.w};
#pragma unroll
            for (int i = 0; i < 4; i++)
#pragma unroll
                for (int j = 0; j < 4; j++)
                    s[i][j] = fmaf(av[i], bv[j], s[i][j]);
        }

        if (jt == qt) {
#pragma unroll
            for (int i = 0; i < 4; i++)
#pragma unroll
                for (int j = 0; j < 4; j++)
                    if (tx * 4 + j > ty * 4 + i) s[i][j] = -1e9f;
        }

#pragma unroll
        for (int i = 0; i < 4; i++) {
            float rm = fmaxf(fmaxf(s[i][0], s[i][1]), fmaxf(s[i][2], s[i][3]));
            rm = fmaxf(rm, __shfl_xor_sync(0xffffffffu, rm, 1));
            rm = fmaxf(rm, __shfl_xor_sync(0xffffffffu, rm, 2));
            rm = fmaxf(rm, __shfl_xor_sync(0xffffffffu, rm, 4));
            rm = fmaxf(rm, __shfl_xor_sync(0xffffffffu, rm, 8));
            float mn = fmaxf(m_i[i], rm);
            float corr = __expf(m_i[i] - mn);
            m_i[i] = mn;
            float rs = 0.0f;
#pragma unroll
            for (int j = 0; j < 4; j++) {
                float p = __expf(s[i][j] - mn);
                s[i][j] = p; rs += p;
            }
            rs += __shfl_xor_sync(0xffffffffu, rs, 1);
            rs += __shfl_xor_sync(0xffffffffu, rs, 2);
            rs += __shfl_xor_sync(0xffffffffu, rs, 4);
            rs += __shfl_xor_sync(0xffffffffu, rs, 8);
            l_i[i] = l_i[i] * corr + rs;
#pragma unroll
            for (int j = 0; j < 4; j++) o_acc[i][j] *= corr;
        }

#pragma unroll
        for (int i = 0; i < 4; i++) {
            float4 p4 = make_float4(s[i][0], s[i][1], s[i][2], s[i][3]);
            *(float4*)&Ps[(ty * 4 + i) * FA_STRIDE + tx * 4] = p4;
        }
        __syncthreads();

#pragma unroll 8
        for (int k = 0; k < 64; k++) {
            float4 vv = *(const float4*)&Vs[k * FA_STRIDE + tx * 4];
            float vb[4] = {vv.x, vv.y, vv.z, vv.w};
            float p0 = Ps[(ty * 4 + 0) * FA_STRIDE + k];
            float p1 = Ps[(ty * 4 + 1) * FA_STRIDE + k];
            float p2 = Ps[(ty * 4 + 2) * FA_STRIDE + k];
            float p3 = Ps[(ty * 4 + 3) * FA_STRIDE + k];
#pragma unroll
            for (int j = 0; j < 4; j++) {
                o_acc[0][j] = fmaf(p0, vb[j], o_acc[0][j]);
                o_acc[1][j] = fmaf(p1, vb[j], o_acc[1][j]);
                o_acc[2][j] = fmaf(p2, vb[j], o_acc[2][j]);
                o_acc[3][j] = fmaf(p3, vb[j], o_acc[3][j]);
            }
        }
    }

    float* Og = g_att + ((size_t)b * S_ + qbase) * U_ + h * DK_;
#pragma unroll
    for (int i = 0; i < 4; i++) {
        float inv = 1.0f / l_i[i];
        float4 o = make_float4(o_acc[i][0] * inv, o_acc[i][1] * inv,
                               o_acc[i][2] * inv, o_acc[i][3] * inv);
        *(float4*)(Og + (size_t)(ty * 4 + i) * U_ + tx * 4) = o;
    }
}

// ---------------------------------------------------------------------------
extern "C" void kernel_launch(void* const* d_in, const int* in_sizes, int n_in,
                              void* d_out, int out_size) {
    const float* query = (const float*)d_in[0];
    const float* key   = (const float*)d_in[1];
    const float* value = (const float*)d_in[2];
    const float* Wq = (const float*)d_in[4];
    const float* bq = (const float*)d_in[5];
    const float* Wk = (const float*)d_in[6];
    const float* bk = (const float*)d_in[7];
    const float* Wv = (const float*)d_in[8];
    const float* bv = (const float*)d_in[9];
    const float* Wo = (const float*)d_in[10];
    const float* bo = (const float*)d_in[11];
    float* out = (float*)d_out;

    cudaFuncSetAttribute(gemm_mma_qkv, cudaFuncAttributeMaxDynamicSharedMemorySize, GT_SMEM);
    cudaFuncSetAttribute(gemm_mma_out, cudaFuncAttributeMaxDynamicSharedMemorySize, GT_SMEM);
    cudaFuncSetAttribute(flash_attn_kernel, cudaFuncAttributeMaxDynamicSharedMemorySize, FA_SMEM);

    dim3 gq(U_ / 128, (B_ * S_) / 128, 3);
    gemm_mma_qkv<<<gq, 256, GT_SMEM>>>(query, key, value, Wq, Wk, Wv, bq, bk, bv);

    dim3 ga(S_ / 64, H_, B_);
    flash_attn_kernel<<<ga, 256, FA_SMEM>>>();

    dim3 go(U_ / 128, (B_ * S_) / 128, 1);
    gemm_mma_out<<<go, 256, GT_SMEM>>>(Wo, bo, out);
}

// round 4
// speedup vs baseline: 2.3273x; 1.6887x over previous
#include <cuda_runtime.h>
#include <cuda_bf16.h>
#include <cstdint>

#define B_  2
#define S_  2048
#define U_  1024
#define H_  16
#define DK_ 64

// scratch (allocation-free rule: __device__ globals)
__device__ float g_q[B_ * S_ * U_];
__device__ float g_k[B_ * S_ * U_];
__device__ float g_v[B_ * S_ * U_];
__device__ float g_att[B_ * S_ * U_];

// ---------------------------------------------------------------------------
// helpers
// ---------------------------------------------------------------------------
__device__ __forceinline__ uint32_t smem_u32(const void* p) {
    uint32_t a;
    asm("{ .reg .u64 t; cvta.to.shared.u64 t, %1; cvt.u32.u64 %0, t; }" : "=r"(a) : "l"(p));
    return a;
}

#define LDSM_X4(r0, r1, r2, r3, addr)                                         \
    asm volatile("ldmatrix.sync.aligned.m8n8.x4.shared.b16 {%0,%1,%2,%3}, [%4];" \
        : "=r"(r0), "=r"(r1), "=r"(r2), "=r"(r3) : "r"(addr))

#define LDSM_X4_T(r0, r1, r2, r3, addr)                                       \
    asm volatile("ldmatrix.sync.aligned.m8n8.x4.trans.shared.b16 {%0,%1,%2,%3}, [%4];" \
        : "=r"(r0), "=r"(r1), "=r"(r2), "=r"(r3) : "r"(addr))

#define MMA_BF16(d, a, b0, b1)                                                \
    asm volatile("mma.sync.aligned.m16n8k16.row.col.f32.bf16.bf16.f32 "       \
        "{%0,%1,%2,%3},{%4,%5,%6,%7},{%8,%9},{%0,%1,%2,%3};"                  \
        : "+f"((d)[0]), "+f"((d)[1]), "+f"((d)[2]), "+f"((d)[3])              \
        : "r"((a)[0]), "r"((a)[1]), "r"((a)[2]), "r"((a)[3]), "r"(b0), "r"(b1))

__device__ __forceinline__ uint32_t pack_bf16(__nv_bfloat16 a, __nv_bfloat16 b) {
    uint32_t ua = *reinterpret_cast<unsigned short*>(&a);
    uint32_t ub = *reinterpret_cast<unsigned short*>(&b);
    return ua | (ub << 16);
}

// split f into (hi, lo) bf16 pairs packed for a float4
__device__ __forceinline__ void cvt_split(const float4& f, uint2& hi, uint2& lo) {
    __nv_bfloat16 h0 = __float2bfloat16(f.x);
    __nv_bfloat16 h1 = __float2bfloat16(f.y);
    __nv_bfloat16 h2 = __float2bfloat16(f.z);
    __nv_bfloat16 h3 = __float2bfloat16(f.w);
    __nv_bfloat16 l0 = __float2bfloat16(f.x - __bfloat162float(h0));
    __nv_bfloat16 l1 = __float2bfloat16(f.y - __bfloat162float(h1));
    __nv_bfloat16 l2 = __float2bfloat16(f.z - __bfloat162float(h2));
    __nv_bfloat16 l3 = __float2bfloat16(f.w - __bfloat162float(h3));
    hi.x = pack_bf16(h0, h1); hi.y = pack_bf16(h2, h3);
    lo.x = pack_bf16(l0, l1); lo.y = pack_bf16(l2, l3);
}

__device__ __forceinline__ void pack_split2(float a, float b, uint32_t& hi, uint32_t& lo) {
    __nv_bfloat16 ha = __float2bfloat16(a), hb = __float2bfloat16(b);
    __nv_bfloat16 la = __float2bfloat16(a - __bfloat162float(ha));
    __nv_bfloat16 lb = __float2bfloat16(b - __bfloat162float(hb));
    hi = pack_bf16(ha, hb); lo = pack_bf16(la, lb);
}

// ---------------------------------------------------------------------------
// split-bf16 mma.sync GEMM (unchanged from round 3 — validated)
// ---------------------------------------------------------------------------
#define KC     32
#define NKC    (U_ / KC)
#define ROWB   80
#define TILE_B (128 * ROWB)
#define ST_ALO (1 * TILE_B)
#define ST_WHI (2 * TILE_B)
#define ST_WLO (3 * TILE_B)
#define STAGE_B (4 * TILE_B)
#define GT_SMEM (2 * STAGE_B)

__device__ void gemm_mma_body(const float* __restrict__ A, const float* __restrict__ W,
                              const float* __restrict__ bias, float* __restrict__ C) {
    extern __shared__ char smem[];
    const int tid  = threadIdx.x;
    const int lane = tid & 31;
    const int wid  = tid >> 5;
    const int wm   = wid >> 2;
    const int wn   = wid & 3;
    const int bm   = blockIdx.y * 128;
    const int bn   = blockIdx.x * 128;

    const int lr = tid >> 1;
    const int lh = tid & 1;
    const float* Ag = A + (size_t)(bm + lr) * U_ + lh * 16;
    const float* Wg = W + (size_t)(bn + lr) * U_ + lh * 16;

    float4 bA[4], bW[4];
#pragma unroll
    for (int q = 0; q < 4; q++) {
        bA[q] = *(const float4*)(Ag + q * 4);
        bW[q] = *(const float4*)(Wg + q * 4);
    }

    float acc[4][4][4];
#pragma unroll
    for (int mf = 0; mf < 4; mf++)
#pragma unroll
        for (int nf = 0; nf < 4; nf++)
#pragma unroll
            for (int r = 0; r < 4; r++) acc[mf][nf][r] = 0.0f;

    const uint32_t sbase  = smem_u32(smem);
    const uint32_t a_row  = (uint32_t)(lane & 15);
    const uint32_t a_colh = (uint32_t)(((lane >> 4) & 1) * 16);
    const uint32_t b_nl   = (uint32_t)((lane & 7) + ((lane >> 4) & 1) * 8);
    const uint32_t b_ks   = (uint32_t)(((lane >> 3) & 1) * 16);

    const uint32_t sts_off = (uint32_t)(lr * ROWB + lh * 32);

    for (int c = 0; c < NKC; c++) {
        char* stp = smem + (size_t)(c & 1) * STAGE_B;
#pragma unroll
        for (int q = 0; q < 4; q++) {
            uint2 hi, lo;
            cvt_split(bA[q], hi, lo);
            *(uint2*)(stp + sts_off + q * 8)          = hi;
            *(uint2*)(stp + ST_ALO + sts_off + q * 8) = lo;
            cvt_split(bW[q], hi, lo);
            *(uint2*)(stp + ST_WHI + sts_off + q * 8) = hi;
            *(uint2*)(stp + ST_WLO + sts_off + q * 8) = lo;
        }
        __syncthreads();
        if (c + 1 < NKC) {
#pragma unroll
            for (int q = 0; q < 4; q++) {
                bA[q] = *(const float4*)(Ag + (c + 1) * KC + q * 4);
                bW[q] = *(const float4*)(Wg + (c + 1) * KC + q * 4);
            }
        }
        const uint32_t st = sbase + (uint32_t)(c & 1) * STAGE_B;
#pragma unroll
        for (int ko = 0; ko < 2; ko++) {
            uint32_t ah[4][4], al[4][4];
#pragma unroll
            for (int mf = 0; mf < 4; mf++) {
                uint32_t ad = st + (uint32_t)((wm * 64 + mf * 16 + a_row) * ROWB)
                                 + (uint32_t)(ko * 32) + a_colh;
                LDSM_X4(ah[mf][0], ah[mf][1], ah[mf][2], ah[mf][3], ad);
                LDSM_X4(al[mf][0], al[mf][1], al[mf][2], al[mf][3], ad + ST_ALO);
            }
            uint32_t bh[2][4], bl[2][4];
#pragma unroll
            for (int np = 0; np < 2; np++) {
                uint32_t bd = st + ST_WHI
                            + (uint32_t)((wn * 32 + np * 16 + b_nl) * ROWB)
                            + (uint32_t)(ko * 32) + b_ks;
                LDSM_X4(bh[np][0], bh[np][1], bh[np][2], bh[np][3], bd);
                LDSM_X4(bl[np][0], bl[np][1], bl[np][2], bl[np][3], bd + TILE_B);
            }
#pragma unroll
            for (int mf = 0; mf < 4; mf++)
#pragma unroll
                for (int nf = 0; nf < 4; nf++) {
                    const uint32_t* bhp = &bh[nf >> 1][(nf & 1) * 2];
                    const uint32_t* blp = &bl[nf >> 1][(nf & 1) * 2];
                    MMA_BF16(acc[mf][nf], ah[mf], bhp[0], bhp[1]);
                    MMA_BF16(acc[mf][nf], ah[mf], blp[0], blp[1]);
                    MMA_BF16(acc[mf][nf], al[mf], bhp[0], bhp[1]);
                }
        }
        __syncthreads();
    }

    const int tr = lane >> 2;
    const int tc = (lane & 3) * 2;
#pragma unroll
    for (int mf = 0; mf < 4; mf++) {
#pragma unroll
        for (int nf = 0; nf < 4; nf++) {
            int gr = bm + wm * 64 + mf * 16 + tr;
            int gc = bn + wn * 32 + nf * 8 + tc;
            float2 bv = *(const float2*)(bias + gc);
            float2 o0 = make_float2(acc[mf][nf][0] + bv.x, acc[mf][nf][1] + bv.y);
            float2 o1 = make_float2(acc[mf][nf][2] + bv.x, acc[mf][nf][3] + bv.y);
            *(float2*)(C + (size_t)gr * U_ + gc)       = o0;
            *(float2*)(C + (size_t)(gr + 8) * U_ + gc) = o1;
        }
    }
}

__global__ __launch_bounds__(256, 1) void gemm_mma_qkv(
    const float* __restrict__ Xq, const float* __restrict__ Xk, const float* __restrict__ Xv,
    const float* __restrict__ Wq, const float* __restrict__ Wk, const float* __restrict__ Wv,
    const float* __restrict__ bq, const float* __restrict__ bk, const float* __restrict__ bv) {
    const float* A; const float* W; const float* bias; float* C;
    if (blockIdx.z == 0)      { A = Xq; W = Wq; bias = bq; C = g_q; }
    else if (blockIdx.z == 1) { A = Xk; W = Wk; bias = bk; C = g_k; }
    else                      { A = Xv; W = Wv; bias = bv; C = g_v; }
    gemm_mma_body(A, W, bias, C);
}

__global__ __launch_bounds__(256, 1) void gemm_mma_out(const float* __restrict__ Wo,
                                                       const float* __restrict__ bo,
                                                       float* __restrict__ out) {
    gemm_mma_body(g_att, Wo, bo, out);
}

// ---------------------------------------------------------------------------
// Flash attention with split-bf16 mma.sync.
// CTA = 128 q-rows x (b,h); kv tiles of 64. 8 warps, each warp = 16 q-rows
// across the full kv/dk width (softmax reductions stay in-warp).
// ---------------------------------------------------------------------------
#define AROWB 144                  // 64 bf16 = 128B + 16B pad
#define AQ_HI 0u
#define AQ_LO 18432u               // 128*144
#define AK_HI 36864u
#define AK_LO 46080u               // +64*144
#define AV_HI 55296u
#define AV_LO 64512u
#define ATT_SMEM 73728

__global__ __launch_bounds__(256, 1) void flash_attn_mma() {
    extern __shared__ char smem[];
    const uint32_t sb = smem_u32(smem);
    const int tid  = threadIdx.x;
    const int lane = tid & 31;
    const int wid  = tid >> 5;
    const int qt   = (int)gridDim.x - 1 - (int)blockIdx.x;   // big tiles first
    const int h    = blockIdx.y;
    const int b    = blockIdx.z;
    const int qbase = qt * 128;

    const float* Qg = g_q + ((size_t)b * S_ + qbase) * U_ + h * DK_;
    const float* Kg = g_k + (size_t)b * S_ * U_ + h * DK_;
    const float* Vg = g_v + (size_t)b * S_ * U_ + h * DK_;

    // load Q tile (pre-scaled), split hi/lo into smem
#pragma unroll
    for (int i = 0; i < 8; i++) {
        int idx = tid + i * 256;
        int row = idx >> 4;
        int c4  = (idx & 15) * 4;
        float4 q = *(const float4*)(Qg + (size_t)row * U_ + c4);
        q.x *= 0.125f; q.y *= 0.125f; q.z *= 0.125f; q.w *= 0.125f;
        uint2 hi, lo;
        cvt_split(q, hi, lo);
        *(uint2*)(smem + AQ_HI + row * AROWB + c4 * 2) = hi;
        *(uint2*)(smem + AQ_LO + row * AROWB + c4 * 2) = lo;
    }

    const uint32_t a_row  = (uint32_t)(lane & 15);
    const uint32_t a_colh = (uint32_t)(((lane >> 4) & 1) * 16);
    const uint32_t b_nl   = (uint32_t)((lane & 7) + ((lane >> 4) & 1) * 8);
    const uint32_t b_ks   = (uint32_t)(((lane >> 3) & 1) * 16);
    const uint32_t v_row  = (uint32_t)(((lane >> 3) & 1) * 8 + (lane & 7));
    const uint32_t v_colh = (uint32_t)(((lane >> 4) & 1) * 16);

    float m0 = -1e30f, m1 = -1e30f, l0 = 0.0f, l1 = 0.0f;
    float oacc[8][4];
#pragma unroll
    for (int nf = 0; nf < 8; nf++)
#pragma unroll
        for (int r = 0; r < 4; r++) oacc[nf][r] = 0.0f;

    const int njt = 2 * qt + 2;
    for (int jt = 0; jt < njt; jt++) {
        const int kbase = jt * 64;
        // stage K/V fp32 into registers (overlaps with prior iter's MMAs)
        float4 kf[4], vf[4];
#pragma unroll
        for (int i = 0; i < 4; i++) {
            int idx = tid + i * 256;
            int row = idx >> 4;
            int c4  = (idx & 15) * 4;
            kf[i] = *(const float4*)(Kg + (size_t)(kbase + row) * U_ + c4);
            vf[i] = *(const float4*)(Vg + (size_t)(kbase + row) * U_ + c4);
        }
        __syncthreads();
#pragma unroll
        for (int i = 0; i < 4; i++) {
            int idx = tid + i * 256;
            int row = idx >> 4;
            int c4  = (idx & 15) * 4;
            uint2 hi, lo;
            cvt_split(kf[i], hi, lo);
            *(uint2*)(smem + AK_HI + row * AROWB + c4 * 2) = hi;
            *(uint2*)(smem + AK_LO + row * AROWB + c4 * 2) = lo;
            cvt_split(vf[i], hi, lo);
            *(uint2*)(smem + AV_HI + row * AROWB + c4 * 2) = hi;
            *(uint2*)(smem + AV_LO + row * AROWB + c4 * 2) = lo;
        }
        __syncthreads();

        // S = Q K^T  (warp: 16 rows x 64 kv cols), 3-pass split
        float sacc[8][4];
#pragma unroll
        for (int j = 0; j < 8; j++)
#pragma unroll
            for (int r = 0; r < 4; r++) sacc[j][r] = 0.0f;

#pragma unroll
        for (int ko = 0; ko < 4; ko++) {
            uint32_t qh[4], ql[4];
            uint32_t ad = sb + AQ_HI + (uint32_t)((wid * 16 + a_row) * AROWB)
                        + (uint32_t)(ko * 32) + a_colh;
            LDSM_X4(qh[0], qh[1], qh[2], qh[3], ad);
            LDSM_X4(ql[0], ql[1], ql[2], ql[3], ad + AQ_LO);
#pragma unroll
            for (int np = 0; np < 4; np++) {
                uint32_t kh[4], kl[4];
                uint32_t bd = sb + AK_HI + (uint32_t)((np * 16 + b_nl) * AROWB)
                            + (uint32_t)(ko * 32) + b_ks;
                LDSM_X4(kh[0], kh[1], kh[2], kh[3], bd);
                LDSM_X4(kl[0], kl[1], kl[2], kl[3], bd + (AK_LO - AK_HI));
#pragma unroll
                for (int half = 0; half < 2; half++) {
                    float* d = sacc[2 * np + half];
                    const uint32_t* bh = &kh[half * 2];
                    const uint32_t* bl = &kl[half * 2];
                    MMA_BF16(d, qh, bh[0], bh[1]);
                    MMA_BF16(d, qh, bl[0], bl[1]);
                    MMA_BF16(d, ql, bh[0], bh[1]);
                }
            }
        }

        // causal mask on the two diagonal-overlapping tiles
        if (jt >= 2 * qt) {
            const int row0 = qbase + wid * 16 + (lane >> 2);
            const int row1 = row0 + 8;
#pragma unroll
            for (int j = 0; j < 8; j++) {
                int col = kbase + 8 * j + 2 * (lane & 3);
                if (col > row0)     sacc[j][0] = -1e9f;
                if (col + 1 > row0) sacc[j][1] = -1e9f;
                if (col > row1)     sacc[j][2] = -1e9f;
                if (col + 1 > row1) sacc[j][3] = -1e9f;
            }
        }

        // online softmax (rows tr and tr+8; quad reduction)
        float rm0 = -1e30f, rm1 = -1e30f;
#pragma unroll
        for (int j = 0; j < 8; j++) {
            rm0 = fmaxf(rm0, fmaxf(sacc[j][0], sacc[j][1]));
            rm1 = fmaxf(rm1, fmaxf(sacc[j][2], sacc[j][3]));
        }
        rm0 = fmaxf(rm0, __shfl_xor_sync(0xffffffffu, rm0, 1));
        rm0 = fmaxf(rm0, __shfl_xor_sync(0xffffffffu, rm0, 2));
        rm1 = fmaxf(rm1, __shfl_xor_sync(0xffffffffu, rm1, 1));
        rm1 = fmaxf(rm1, __shfl_xor_sync(0xffffffffu, rm1, 2));
        float mn0 = fmaxf(m0, rm0), mn1 = fmaxf(m1, rm1);
        float corr0 = __expf(m0 - mn0), corr1 = __expf(m1 - mn1);
        m0 = mn0; m1 = mn1;
        float rs0 = 0.0f, rs1 = 0.0f;
#pragma unroll
        for (int j = 0; j < 8; j++) {
            float p0 = __expf(sacc[j][0] - mn0);
            float p1 = __expf(sacc[j][1] - mn0);
            float p2 = __expf(sacc[j][2] - mn1);
            float p3 = __expf(sacc[j][3] - mn1);
            sacc[j][0] = p0; sacc[j][1] = p1; sacc[j][2] = p2; sacc[j][3] = p3;
            rs0 += p0 + p1; rs1 += p2 + p3;
        }
        rs0 += __shfl_xor_sync(0xffffffffu, rs0, 1);
        rs0 += __shfl_xor_sync(0xffffffffu, rs0, 2);
        rs1 += __shfl_xor_sync(0xffffffffu, rs1, 1);
        rs1 += __shfl_xor_sync(0xffffffffu, rs1, 2);
        l0 = l0 * corr0 + rs0;
        l1 = l1 * corr1 + rs1;
#pragma unroll
        for (int nf = 0; nf < 8; nf++) {
            oacc[nf][0] *= corr0; oacc[nf][1] *= corr0;
            oacc[nf][2] *= corr1; oacc[nf][3] *= corr1;
        }

        // O += P V  (P split in registers, V split from smem via trans ldmatrix)
#pragma unroll
        for (int t = 0; t < 4; t++) {
            uint32_t ph[4], pl[4];
            pack_split2(sacc[2 * t][0],     sacc[2 * t][1],     ph[0], pl[0]);
            pack_split2(sacc[2 * t][2],     sacc[2 * t][3],     ph[1], pl[1]);
            pack_split2(sacc[2 * t + 1][0], sacc[2 * t + 1][1], ph[2], pl[2]);
            pack_split2(sacc[2 * t + 1][2], sacc[2 * t + 1][3], ph[3], pl[3]);
            uint32_t vh[4][4], vl[4][4];
#pragma unroll
            for (int g = 0; g < 4; g++) {
                uint32_t va = sb + AV_HI + (uint32_t)((t * 16 + v_row) * AROWB)
                            + v_colh + (uint32_t)(g * 32);
                LDSM_X4_T(vh[g][0], vh[g][1], vh[g][2], vh[g][3], va);
                LDSM_X4_T(vl[g][0], vl[g][1], vl[g][2], vl[g][3], va + (AV_LO - AV_HI));
            }
#pragma unroll
            for (int nf = 0; nf < 8; nf++) {
                const int g = nf >> 1;
                const uint32_t* bh = &vh[g][(nf & 1) * 2];
                const uint32_t* bl = &vl[g][(nf & 1) * 2];
                MMA_BF16(oacc[nf], ph, bh[0], bh[1]);
                MMA_BF16(oacc[nf], pl, bh[0], bh[1]);
                MMA_BF16(oacc[nf], ph, bl[0], bl[1]);
            }
        }
    }

    // epilogue
    const float inv0 = 1.0f / l0, inv1 = 1.0f / l1;
    const int row0 = qbase + wid * 16 + (lane >> 2);
    float* Og = g_att + ((size_t)b * S_ + row0) * U_ + h * DK_ + 2 * (lane & 3);
#pragma unroll
    for (int nf = 0; nf < 8; nf++) {
        *(float2*)(Og + 8 * nf)            = make_float2(oacc[nf][0] * inv0, oacc[nf][1] * inv0);
        *(float2*)(Og + 8 * U_ + 8 * nf)   = make_float2(oacc[nf][2] * inv1, oacc[nf][3] * inv1);
    }
}

// ---------------------------------------------------------------------------
extern "C" void kernel_launch(void* const* d_in, const int* in_sizes, int n_in,
                              void* d_out, int out_size) {
    const float* query = (const float*)d_in[0];
    const float* key   = (const float*)d_in[1];
    const float* value = (const float*)d_in[2];
    const float* Wq = (const float*)d_in[4];
    const float* bq = (const float*)d_in[5];
    const float* Wk = (const float*)d_in[6];
    const float* bk = (const float*)d_in[7];
    const float* Wv = (const float*)d_in[8];
    const float* bv = (const float*)d_in[9];
    const float* Wo = (const float*)d_in[10];
    const float* bo = (const float*)d_in[11];
    float* out = (float*)d_out;

    cudaFuncSetAttribute(gemm_mma_qkv, cudaFuncAttributeMaxDynamicSharedMemorySize, GT_SMEM);
    cudaFuncSetAttribute(gemm_mma_out, cudaFuncAttributeMaxDynamicSharedMemorySize, GT_SMEM);
    cudaFuncSetAttribute(flash_attn_mma, cudaFuncAttributeMaxDynamicSharedMemorySize, ATT_SMEM);

    dim3 gq(U_ / 128, (B_ * S_) / 128, 3);
    gemm_mma_qkv<<<gq, 256, GT_SMEM>>>(query, key, value, Wq, Wk, Wv, bq, bk, bv);

    dim3 ga(S_ / 128, H_, B_);
    flash_attn_mma<<<ga, 256, ATT_SMEM>>>();

    dim3 go(U_ / 128, (B_ * S_) / 128, 1);
    gemm_mma_out<<<go, 256, GT_SMEM>>>(Wo, bo, out);
}

// round 5
// speedup vs baseline: 2.4064x; 1.0340x over previous
#include <cuda_runtime.h>
#include <cuda_bf16.h>
#include <cstdint>

#define B_  2
#define S_  2048
#define U_  1024
#define H_  16
#define DK_ 64
#define BS_ (B_ * S_)

// persistent split-bf16 scratch (allocation-free rule: __device__ globals)
__device__ __nv_bfloat16 in_q_hi[BS_ * U_], in_q_lo[BS_ * U_];
__device__ __nv_bfloat16 in_k_hi[BS_ * U_], in_k_lo[BS_ * U_];
__device__ __nv_bfloat16 in_v_hi[BS_ * U_], in_v_lo[BS_ * U_];
__device__ __nv_bfloat16 w_q_hi[U_ * U_], w_q_lo[U_ * U_];
__device__ __nv_bfloat16 w_k_hi[U_ * U_], w_k_lo[U_ * U_];
__device__ __nv_bfloat16 w_v_hi[U_ * U_], w_v_lo[U_ * U_];
__device__ __nv_bfloat16 w_o_hi[U_ * U_], w_o_lo[U_ * U_];
__device__ __nv_bfloat16 g_q_hi[BS_ * U_], g_q_lo[BS_ * U_];
__device__ __nv_bfloat16 g_k_hi[BS_ * U_], g_k_lo[BS_ * U_];
__device__ __nv_bfloat16 g_v_hi[BS_ * U_], g_v_lo[BS_ * U_];
__device__ __nv_bfloat16 g_att_hi[BS_ * U_], g_att_lo[BS_ * U_];

// ---------------------------------------------------------------------------
// helpers
// ---------------------------------------------------------------------------
__device__ __forceinline__ uint32_t smem_u32(const void* p) {
    uint32_t a;
    asm("{ .reg .u64 t; cvta.to.shared.u64 t, %1; cvt.u32.u64 %0, t; }" : "=r"(a) : "l"(p));
    return a;
}

#define LDSM_X4(r0, r1, r2, r3, addr)                                         \
    asm volatile("ldmatrix.sync.aligned.m8n8.x4.shared.b16 {%0,%1,%2,%3}, [%4];" \
        : "=r"(r0), "=r"(r1), "=r"(r2), "=r"(r3) : "r"(addr))

#define LDSM_X4_T(r0, r1, r2, r3, addr)                                       \
    asm volatile("ldmatrix.sync.aligned.m8n8.x4.trans.shared.b16 {%0,%1,%2,%3}, [%4];" \
        : "=r"(r0), "=r"(r1), "=r"(r2), "=r"(r3) : "r"(addr))

#define MMA_BF16(d, a, b0, b1)                                                \
    asm volatile("mma.sync.aligned.m16n8k16.row.col.f32.bf16.bf16.f32 "       \
        "{%0,%1,%2,%3},{%4,%5,%6,%7},{%8,%9},{%0,%1,%2,%3};"                  \
        : "+f"((d)[0]), "+f"((d)[1]), "+f"((d)[2]), "+f"((d)[3])              \
        : "r"((a)[0]), "r"((a)[1]), "r"((a)[2]), "r"((a)[3]), "r"(b0), "r"(b1))

#define CP_ASYNC16(saddr, gptr) \
    asm volatile("cp.async.cg.shared.global [%0], [%1], 16;" :: "r"(saddr), "l"(gptr) : "memory")
#define CP_COMMIT() asm volatile("cp.async.commit_group;" ::: "memory")
template <int N> __device__ __forceinline__ void cp_wait() {
    asm volatile("cp.async.wait_group %0;" :: "n"(N) : "memory");
}

__device__ __forceinline__ uint32_t pack_bf16(__nv_bfloat16 a, __nv_bfloat16 b) {
    uint32_t ua = *reinterpret_cast<unsigned short*>(&a);
    uint32_t ub = *reinterpret_cast<unsigned short*>(&b);
    return ua | (ub << 16);
}

__device__ __forceinline__ void cvt_split(const float4& f, uint2& hi, uint2& lo) {
    __nv_bfloat16 h0 = __float2bfloat16(f.x);
    __nv_bfloat16 h1 = __float2bfloat16(f.y);
    __nv_bfloat16 h2 = __float2bfloat16(f.z);
    __nv_bfloat16 h3 = __float2bfloat16(f.w);
    __nv_bfloat16 l0 = __float2bfloat16(f.x - __bfloat162float(h0));
    __nv_bfloat16 l1 = __float2bfloat16(f.y - __bfloat162float(h1));
    __nv_bfloat16 l2 = __float2bfloat16(f.z - __bfloat162float(h2));
    __nv_bfloat16 l3 = __float2bfloat16(f.w - __bfloat162float(h3));
    hi.x = pack_bf16(h0, h1); hi.y = pack_bf16(h2, h3);
    lo.x = pack_bf16(l0, l1); lo.y = pack_bf16(l2, l3);
}

__device__ __forceinline__ void pack_split2(float a, float b, uint32_t& hi, uint32_t& lo) {
    __nv_bfloat16 ha = __float2bfloat16(a), hb = __float2bfloat16(b);
    __nv_bfloat16 la = __float2bfloat16(a - __bfloat162float(ha));
    __nv_bfloat16 lb = __float2bfloat16(b - __bfloat162float(hb));
    hi = pack_bf16(ha, hb); lo = pack_bf16(la, lb);
}

// ---------------------------------------------------------------------------
// pre-pass: fp32 -> (hi, lo) bf16
// ---------------------------------------------------------------------------
__global__ __launch_bounds__(256) void convert_split_kernel(
    const float* __restrict__ src, __nv_bfloat16* __restrict__ hi,
    __nv_bfloat16* __restrict__ lo, int n4) {
    int i = blockIdx.x * blockDim.x + threadIdx.x;
    if (i < n4) {
        float4 f = ((const float4*)src)[i];
        uint2 h, l;
        cvt_split(f, h, l);
        ((uint2*)hi)[i] = h;
        ((uint2*)lo)[i] = l;
    }
}

// ---------------------------------------------------------------------------
// split-bf16 GEMM, cp.async 3-stage: C = A @ W^T + bias  (operands pre-split)
// CTA 128x128, 8 warps (2x4), warp tile 64x32, K-chunk 32.
// stage layout: Ahi @0, Alo @10240, Whi @20480, Wlo @30720 (row stride 80B)
// ---------------------------------------------------------------------------
#define ROWB    80
#define TILE_B  10240
#define STAGE_B 40960
#define G_SMEM  (3 * STAGE_B)
#define NKC     (U_ / 32)

__device__ __forceinline__ void g_issue(uint32_t st,
                                        const __nv_bfloat16* __restrict__ Ah,
                                        const __nv_bfloat16* __restrict__ Al,
                                        const __nv_bfloat16* __restrict__ Wh,
                                        const __nv_bfloat16* __restrict__ Wl,
                                        int bm, int bn, int k0, int tid) {
#pragma unroll
    for (int i = 0; i < 2; i++) {
        int id  = tid * 2 + i;
        int row = id >> 2, seg = id & 3;
        uint32_t so = (uint32_t)(row * ROWB + seg * 16);
        size_t goA = (size_t)(bm + row) * U_ + k0 + seg * 8;
        size_t goW = (size_t)(bn + row) * U_ + k0 + seg * 8;
        CP_ASYNC16(st + so,              Ah + goA);
        CP_ASYNC16(st + 10240u + so,     Al + goA);
        CP_ASYNC16(st + 20480u + so,     Wh + goW);
        CP_ASYNC16(st + 30720u + so,     Wl + goW);
    }
}

template <bool SPLIT_OUT>
__device__ void gemm_bf_body(const __nv_bfloat16* __restrict__ Ah,
                             const __nv_bfloat16* __restrict__ Al,
                             const __nv_bfloat16* __restrict__ Wh,
                             const __nv_bfloat16* __restrict__ Wl,
                             const float* __restrict__ bias, float scale,
                             float* __restrict__ Cf,
                             __nv_bfloat16* __restrict__ Ch,
                             __nv_bfloat16* __restrict__ Cl) {
    extern __shared__ char smem[];
    const int tid  = threadIdx.x;
    const int lane = tid & 31;
    const int wid  = tid >> 5;
    const int wm   = wid >> 2;
    const int wn   = wid & 3;
    const int bm   = blockIdx.y * 128;
    const int bn   = blockIdx.x * 128;
    const uint32_t sbase = smem_u32(smem);

    float acc[4][4][4];
#pragma unroll
    for (int mf = 0; mf < 4; mf++)
#pragma unroll
        for (int nf = 0; nf < 4; nf++)
#pragma unroll
            for (int r = 0; r < 4; r++) acc[mf][nf][r] = 0.0f;

    const uint32_t a_row  = (uint32_t)(lane & 15);
    const uint32_t a_colh = (uint32_t)(((lane >> 4) & 1) * 16);
    const uint32_t b_nl   = (uint32_t)((lane & 7) + ((lane >> 4) & 1) * 8);
    const uint32_t b_ks   = (uint32_t)(((lane >> 3) & 1) * 16);

    g_issue(sbase, Ah, Al, Wh, Wl, bm, bn, 0, tid);  CP_COMMIT();
    g_issue(sbase + STAGE_B, Ah, Al, Wh, Wl, bm, bn, 32, tid);  CP_COMMIT();

    for (int c = 0; c < NKC; c++) {
        if (c + 2 < NKC)
            g_issue(sbase + (uint32_t)((c + 2) % 3) * STAGE_B, Ah, Al, Wh, Wl,
                    bm, bn, (c + 2) * 32, tid);
        CP_COMMIT();
        cp_wait<2>();
        __syncthreads();

        const uint32_t st = sbase + (uint32_t)(c % 3) * STAGE_B;
#pragma unroll
        for (int ko = 0; ko < 2; ko++) {
            uint32_t ah[4][4], al[4][4];
#pragma unroll
            for (int mf = 0; mf < 4; mf++) {
                uint32_t ad = st + (uint32_t)((wm * 64 + mf * 16 + a_row) * ROWB)
                                 + (uint32_t)(ko * 32) + a_colh;
                LDSM_X4(ah[mf][0], ah[mf][1], ah[mf][2], ah[mf][3], ad);
                LDSM_X4(al[mf][0], al[mf][1], al[mf][2], al[mf][3], ad + 10240u);
            }
            uint32_t bh[2][4], bl[2][4];
#pragma unroll
            for (int np = 0; np < 2; np++) {
                uint32_t bd = st + 20480u
                            + (uint32_t)((wn * 32 + np * 16 + b_nl) * ROWB)
                            + (uint32_t)(ko * 32) + b_ks;
                LDSM_X4(bh[np][0], bh[np][1], bh[np][2], bh[np][3], bd);
                LDSM_X4(bl[np][0], bl[np][1], bl[np][2], bl[np][3], bd + 10240u);
            }
#pragma unroll
            for (int mf = 0; mf < 4; mf++)
#pragma unroll
                for (int nf = 0; nf < 4; nf++) {
                    const uint32_t* bhp = &bh[nf >> 1][(nf & 1) * 2];
                    const uint32_t* blp = &bl[nf >> 1][(nf & 1) * 2];
                    MMA_BF16(acc[mf][nf], ah[mf], bhp[0], bhp[1]);
                    MMA_BF16(acc[mf][nf], ah[mf], blp[0], blp[1]);
                    MMA_BF16(acc[mf][nf], al[mf], bhp[0], bhp[1]);
                }
        }
        __syncthreads();
    }

    const int tr = lane >> 2;
    const int tc = (lane & 3) * 2;
#pragma unroll
    for (int mf = 0; mf < 4; mf++) {
#pragma unroll
        for (int nf = 0; nf < 4; nf++) {
            int gr = bm + wm * 64 + mf * 16 + tr;
            int gc = bn + wn * 32 + nf * 8 + tc;
            float2 bv = *(const float2*)(bias + gc);
            if (SPLIT_OUT) {
                float a0 = (acc[mf][nf][0] + bv.x) * scale;
                float a1 = (acc[mf][nf][1] + bv.y) * scale;
                float a2 = (acc[mf][nf][2] + bv.x) * scale;
                float a3 = (acc[mf][nf][3] + bv.y) * scale;
                uint32_t h, l;
                pack_split2(a0, a1, h, l);
                *(uint32_t*)(Ch + (size_t)gr * U_ + gc) = h;
                *(uint32_t*)(Cl + (size_t)gr * U_ + gc) = l;
                pack_split2(a2, a3, h, l);
                *(uint32_t*)(Ch + (size_t)(gr + 8) * U_ + gc) = h;
                *(uint32_t*)(Cl + (size_t)(gr + 8) * U_ + gc) = l;
            } else {
                float2 o0 = make_float2(acc[mf][nf][0] + bv.x, acc[mf][nf][1] + bv.y);
                float2 o1 = make_float2(acc[mf][nf][2] + bv.x, acc[mf][nf][3] + bv.y);
                *(float2*)(Cf + (size_t)gr * U_ + gc)       = o0;
                *(float2*)(Cf + (size_t)(gr + 8) * U_ + gc) = o1;
            }
        }
    }
}

__global__ __launch_bounds__(256, 1) void gemm_bf_qkv() {
    if (blockIdx.z == 0)
        gemm_bf_body<true>(in_q_hi, in_q_lo, w_q_hi, w_q_lo, nullptr, 0.125f,
                           nullptr, g_q_hi, g_q_lo);
    else if (blockIdx.z == 1)
        gemm_bf_body<true>(in_k_hi, in_k_lo, w_k_hi, w_k_lo, nullptr, 1.0f,
                           nullptr, g_k_hi, g_k_lo);
    else
        gemm_bf_body<true>(in_v_hi, in_v_lo, w_v_hi, w_v_lo, nullptr, 1.0f,
                           nullptr, g_v_hi, g_v_lo);
}
// bias passed via __constant__-free route: we must pass real bias pointers.
// (specialized wrappers below carry bias pointers as arguments)
__global__ __launch_bounds__(256, 1) void gemm_bf_qkv_b(
    const float* __restrict__ bq, const float* __restrict__ bk,
    const float* __restrict__ bv) {
    if (blockIdx.z == 0)
        gemm_bf_body<true>(in_q_hi, in_q_lo, w_q_hi, w_q_lo, bq, 0.125f,
                           nullptr, g_q_hi, g_q_lo);
    else if (blockIdx.z == 1)
        gemm_bf_body<true>(in_k_hi, in_k_lo, w_k_hi, w_k_lo, bk, 1.0f,
                           nullptr, g_k_hi, g_k_lo);
    else
        gemm_bf_body<true>(in_v_hi, in_v_lo, w_v_hi, w_v_lo, bv, 1.0f,
                           nullptr, g_v_hi, g_v_lo);
}

__global__ __launch_bounds__(256, 1) void gemm_bf_out(const float* __restrict__ bo,
                                                      float* __restrict__ out) {
    gemm_bf_body<false>(g_att_hi, g_att_lo, w_o_hi, w_o_lo, bo, 1.0f,
                        out, nullptr, nullptr);
}

// ---------------------------------------------------------------------------
// Flash attention, split-bf16 mma.sync, cp.async double-buffered K/V.
// CTA = 128 q-rows x (b,h); kv tiles of 64. 8 warps x 16 q-rows.
// smem: Qhi @0, Qlo @18432; stages @36864 (+36864): Khi 0/Klo 9216/Vhi 18432/Vlo 27648
// ---------------------------------------------------------------------------
#define AROWB    144
#define AQ_LO_O  18432u
#define AST0     36864u
#define ASTAGE_B 36864u
#define ATT_SMEM 110592

__device__ __forceinline__ void kv_issue(uint32_t buf,
                                         const __nv_bfloat16* __restrict__ Kh,
                                         const __nv_bfloat16* __restrict__ Kl,
                                         const __nv_bfloat16* __restrict__ Vh,
                                         const __nv_bfloat16* __restrict__ Vl,
                                         int kbase, int tid) {
#pragma unroll
    for (int i = 0; i < 2; i++) {
        int id  = tid * 2 + i;
        int row = id >> 3, seg = id & 7;
        uint32_t so = (uint32_t)(row * AROWB + seg * 16);
        size_t go = (size_t)(kbase + row) * U_ + seg * 8;
        CP_ASYNC16(buf + so,          Kh + go);
        CP_ASYNC16(buf + 9216u + so,  Kl + go);
        CP_ASYNC16(buf + 18432u + so, Vh + go);
        CP_ASYNC16(buf + 27648u + so, Vl + go);
    }
}

__global__ __launch_bounds__(256, 1) void flash_attn_mma() {
    extern __shared__ char smem[];
    const uint32_t sb = smem_u32(smem);
    const int tid  = threadIdx.x;
    const int lane = tid & 31;
    const int wid  = tid >> 5;
    const int qt   = (int)gridDim.x - 1 - (int)blockIdx.x;   // big tiles first
    const int h    = blockIdx.y;
    const int b    = blockIdx.z;
    const int qbase = qt * 128;

    const size_t head_off = (size_t)b * S_ * U_ + h * DK_;
    const __nv_bfloat16* Qh = g_q_hi + head_off + (size_t)qbase * U_;
    const __nv_bfloat16* Ql = g_q_lo + head_off + (size_t)qbase * U_;
    const __nv_bfloat16* Kh = g_k_hi + head_off;
    const __nv_bfloat16* Kl = g_k_lo + head_off;
    const __nv_bfloat16* Vh = g_v_hi + head_off;
    const __nv_bfloat16* Vl = g_v_lo + head_off;

    // Q tile cp.async (one-time)
#pragma unroll
    for (int i = 0; i < 4; i++) {
        int id  = tid * 4 + i;
        int row = id >> 3, seg = id & 7;
        uint32_t so = (uint32_t)(row * AROWB + seg * 16);
        size_t go = (size_t)row * U_ + seg * 8;
        CP_ASYNC16(sb + so,           Qh + go);
        CP_ASYNC16(sb + AQ_LO_O + so, Ql + go);
    }
    CP_COMMIT();
    kv_issue(sb + AST0, Kh, Kl, Vh, Vl, 0, tid);
    CP_COMMIT();

    const uint32_t a_row  = (uint32_t)(lane & 15);
    const uint32_t a_colh = (uint32_t)(((lane >> 4) & 1) * 16);
    const uint32_t b_nl   = (uint32_t)((lane & 7) + ((lane >> 4) & 1) * 8);
    const uint32_t b_ks   = (uint32_t)(((lane >> 3) & 1) * 16);
    const uint32_t v_row  = (uint32_t)(((lane >> 3) & 1) * 8 + (lane & 7));
    const uint32_t v_colh = (uint32_t)(((lane >> 4) & 1) * 16);

    // hoist Q fragments to registers
    cp_wait<1>();
    __syncthreads();
    uint32_t qh[4][4], ql[4][4];
#pragma unroll
    for (int ko = 0; ko < 4; ko++) {
        uint32_t ad = sb + (uint32_t)((wid * 16 + a_row) * AROWB)
                    + (uint32_t)(ko * 32) + a_colh;
        LDSM_X4(qh[ko][0], qh[ko][1], qh[ko][2], qh[ko][3], ad);
        LDSM_X4(ql[ko][0], ql[ko][1], ql[ko][2], ql[ko][3], ad + AQ_LO_O);
    }

    float m0 = -1e30f, m1 = -1e30f, l0 = 0.0f, l1 = 0.0f;
    float oacc[8][4];
#pragma unroll
    for (int nf = 0; nf < 8; nf++)
#pragma unroll
        for (int r = 0; r < 4; r++) oacc[nf][r] = 0.0f;

    const int njt = 2 * qt + 2;
    for (int jt = 0; jt < njt; jt++) {
        const int kbase = jt * 64;
        if (jt + 1 < njt)
            kv_issue(sb + AST0 + (uint32_t)((jt + 1) & 1) * ASTAGE_B,
                     Kh, Kl, Vh, Vl, (jt + 1) * 64, tid);
        CP_COMMIT();
        cp_wait<1>();
        __syncthreads();

        const uint32_t st = sb + AST0 + (uint32_t)(jt & 1) * ASTAGE_B;

        // S = Q K^T
        float sacc[8][4];
#pragma unroll
        for (int j = 0; j < 8; j++)
#pragma unroll
            for (int r = 0; r < 4; r++) sacc[j][r] = 0.0f;

#pragma unroll
        for (int ko = 0; ko < 4; ko++) {
#pragma unroll
            for (int np = 0; np < 4; np++) {
                uint32_t kh[4], kl[4];
                uint32_t bd = st + (uint32_t)((np * 16 + b_nl) * AROWB)
                            + (uint32_t)(ko * 32) + b_ks;
                LDSM_X4(kh[0], kh[1], kh[2], kh[3], bd);
                LDSM_X4(kl[0], kl[1], kl[2], kl[3], bd + 9216u);
#pragma unroll
                for (int half = 0; half < 2; half++) {
                    float* d = sacc[2 * np + half];
                    const uint32_t* bh = &kh[half * 2];
                    const uint32_t* bl = &kl[half * 2];
                    MMA_BF16(d, qh[ko], bh[0], bh[1]);
                    MMA_BF16(d, qh[ko], bl[0], bl[1]);
                    MMA_BF16(d, ql[ko], bh[0], bh[1]);
                }
            }
        }

        // causal mask on diagonal-overlapping tiles
        if (jt >= 2 * qt) {
            const int row0 = qbase + wid * 16 + (lane >> 2);
            const int row1 = row0 + 8;
#pragma unroll
            for (int j = 0; j < 8; j++) {
                int col = kbase + 8 * j + 2 * (lane & 3);
                if (col > row0)     sacc[j][0] = -1e9f;
                if (col + 1 > row0) sacc[j][1] = -1e9f;
                if (col > row1)     sacc[j][2] = -1e9f;
                if (col + 1 > row1) sacc[j][3] = -1e9f;
            }
        }

        // online softmax (in-warp quad reductions)
        float rm0 = -1e30f, rm1 = -1e30f;
#pragma unroll
        for (int j = 0; j < 8; j++) {
            rm0 = fmaxf(rm0, fmaxf(sacc[j][0], sacc[j][1]));
            rm1 = fmaxf(rm1, fmaxf(sacc[j][2], sacc[j][3]));
        }
        rm0 = fmaxf(rm0, __shfl_xor_sync(0xffffffffu, rm0, 1));
        rm0 = fmaxf(rm0, __shfl_xor_sync(0xffffffffu, rm0, 2));
        rm1 = fmaxf(rm1, __shfl_xor_sync(0xffffffffu, rm1, 1));
        rm1 = fmaxf(rm1, __shfl_xor_sync(0xffffffffu, rm1, 2));
        float mn0 = fmaxf(m0, rm0), mn1 = fmaxf(m1, rm1);
        float corr0 = __expf(m0 - mn0), corr1 = __expf(m1 - mn1);
        m0 = mn0; m1 = mn1;
        float rs0 = 0.0f, rs1 = 0.0f;
#pragma unroll
        for (int j = 0; j < 8; j++) {
            float p0 = __expf(sacc[j][0] - mn0);
            float p1 = __expf(sacc[j][1] - mn0);
            float p2 = __expf(sacc[j][2] - mn1);
            float p3 = __expf(sacc[j][3] - mn1);
            sacc[j][0] = p0; sacc[j][1] = p1; sacc[j][2] = p2; sacc[j][3] = p3;
            rs0 += p0 + p1; rs1 += p2 + p3;
        }
        rs0 += __shfl_xor_sync(0xffffffffu, rs0, 1);
        rs0 += __shfl_xor_sync(0xffffffffu, rs0, 2);
        rs1 += __shfl_xor_sync(0xffffffffu, rs1, 1);
        rs1 += __shfl_xor_sync(0xffffffffu, rs1, 2);
        l0 = l0 * corr0 + rs0;
        l1 = l1 * corr1 + rs1;
#pragma unroll
        for (int nf = 0; nf < 8; nf++) {
            oacc[nf][0] *= corr0; oacc[nf][1] *= corr0;
            oacc[nf][2] *= corr1; oacc[nf][3] *= corr1;
        }

        // O += P V
#pragma unroll
        for (int t = 0; t < 4; t++) {
            uint32_t ph[4], pl[4];
            pack_split2(sacc[2 * t][0],     sacc[2 * t][1],     ph[0], pl[0]);
            pack_split2(sacc[2 * t][2],     sacc[2 * t][3],     ph[1], pl[1]);
            pack_split2(sacc[2 * t + 1][0], sacc[2 * t + 1][1], ph[2], pl[2]);
            pack_split2(sacc[2 * t + 1][2], sacc[2 * t + 1][3], ph[3], pl[3]);
            uint32_t vh[4][4], vl[4][4];
#pragma unroll
            for (int g = 0; g < 4; g++) {
                uint32_t va = st + 18432u + (uint32_t)((t * 16 + v_row) * AROWB)
                            + v_colh + (uint32_t)(g * 32);
                LDSM_X4_T(vh[g][0], vh[g][1], vh[g][2], vh[g][3], va);
                LDSM_X4_T(vl[g][0], vl[g][1], vl[g][2], vl[g][3], va + 9216u);
            }
#pragma unroll
            for (int nf = 0; nf < 8; nf++) {
                const int g = nf >> 1;
                const uint32_t* bh = &vh[g][(nf & 1) * 2];
                const uint32_t* bl = &vl[g][(nf & 1) * 2];
                MMA_BF16(oacc[nf], ph, bh[0], bh[1]);
                MMA_BF16(oacc[nf], pl, bh[0], bh[1]);
                MMA_BF16(oacc[nf], ph, bl[0], bl[1]);
            }
        }
        __syncthreads();
    }

    // epilogue: normalize, split, write g_att hi/lo
    const float inv0 = 1.0f / l0, inv1 = 1.0f / l1;
    const int row0 = qbase + wid * 16 + (lane >> 2);
    const size_t obase = (size_t)b * S_ * U_ + (size_t)row0 * U_ + h * DK_ + 2 * (lane & 3);
#pragma unroll
    for (int nf = 0; nf < 8; nf++) {
        uint32_t h32, l32;
        pack_split2(oacc[nf][0] * inv0, oacc[nf][1] * inv0, h32, l32);
        *(uint32_t*)(g_att_hi + obase + 8 * nf) = h32;
        *(uint32_t*)(g_att_lo + obase + 8 * nf) = l32;
        pack_split2(oacc[nf][2] * inv1, oacc[nf][3] * inv1, h32, l32);
        *(uint32_t*)(g_att_hi + obase + 8 * (size_t)U_ + 8 * nf) = h32;
        *(uint32_t*)(g_att_lo + obase + 8 * (size_t)U_ + 8 * nf) = l32;
    }
}

// ---------------------------------------------------------------------------
extern "C" void kernel_launch(void* const* d_in, const int* in_sizes, int n_in,
                              void* d_out, int out_size) {
    const float* query = (const float*)d_in[0];
    const float* key   = (const float*)d_in[1];
    const float* value = (const float*)d_in[2];
    const float* Wq = (const float*)d_in[4];
    const float* bq = (const float*)d_in[5];
    const float* Wk = (const float*)d_in[6];
    const float* bk = (const float*)d_in[7];
    const float* Wv = (const float*)d_in[8];
    const float* bv = (const float*)d_in[9];
    const float* Wo = (const float*)d_in[10];
    const float* bo = (const float*)d_in[11];
    float* out = (float*)d_out;

    cudaFuncSetAttribute(gemm_bf_qkv_b, cudaFuncAttributeMaxDynamicSharedMemorySize, G_SMEM);
    cudaFuncSetAttribute(gemm_bf_out, cudaFuncAttributeMaxDynamicSharedMemorySize, G_SMEM);
    cudaFuncSetAttribute(flash_attn_mma, cudaFuncAttributeMaxDynamicSharedMemorySize, ATT_SMEM);

    // resolve device-global addresses (host-side, not captured)
    static __nv_bfloat16 *p_iqh = nullptr, *p_iql, *p_ikh, *p_ikl, *p_ivh, *p_ivl;
    static __nv_bfloat16 *p_wqh, *p_wql, *p_wkh, *p_wkl, *p_wvh, *p_wvl, *p_woh, *p_wol;
    if (!p_iqh) {
        cudaGetSymbolAddress((void**)&p_iqh, in_q_hi);
        cudaGetSymbolAddress((void**)&p_iql, in_q_lo);
        cudaGetSymbolAddress((void**)&p_ikh, in_k_hi);
        cudaGetSymbolAddress((void**)&p_ikl, in_k_lo);
        cudaGetSymbolAddress((void**)&p_ivh, in_v_hi);
        cudaGetSymbolAddress((void**)&p_ivl, in_v_lo);
        cudaGetSymbolAddress((void**)&p_wqh, w_q_hi);
        cudaGetSymbolAddress((void**)&p_wql, w_q_lo);
        cudaGetSymbolAddress((void**)&p_wkh, w_k_hi);
        cudaGetSymbolAddress((void**)&p_wkl, w_k_lo);
        cudaGetSymbolAddress((void**)&p_wvh, w_v_hi);
        cudaGetSymbolAddress((void**)&p_wvl, w_v_lo);
        cudaGetSymbolAddress((void**)&p_woh, w_o_hi);
        cudaGetSymbolAddress((void**)&p_wol, w_o_lo);
    }

    const int nact4 = (BS_ * U_) / 4;   // 1,048,576
    const int nw4   = (U_ * U_) / 4;    // 262,144
    convert_split_kernel<<<nact4 / 256, 256>>>(query, p_iqh, p_iql, nact4);
    convert_split_kernel<<<nact4 / 256, 256>>>(key,   p_ikh, p_ikl, nact4);
    convert_split_kernel<<<nact4 / 256, 256>>>(value, p_ivh, p_ivl, nact4);
    convert_split_kernel<<<nw4 / 256, 256>>>(Wq, p_wqh, p_wql, nw4);
    convert_split_kernel<<<nw4 / 256, 256>>>(Wk, p_wkh, p_wkl, nw4);
    convert_split_kernel<<<nw4 / 256, 256>>>(Wv, p_wvh, p_wvl, nw4);
    convert_split_kernel<<<nw4 / 256, 256>>>(Wo, p_woh, p_wol, nw4);

    dim3 gq(U_ / 128, BS_ / 128, 3);
    gemm_bf_qkv_b<<<gq, 256, G_SMEM>>>(bq, bk, bv);

    dim3 ga(S_ / 128, H_, B_);
    flash_attn_mma<<<ga, 256, ATT_SMEM>>>();

    dim3 go(U_ / 128, BS_ / 128, 1);
    gemm_bf_out<<<go, 256, G_SMEM>>>(bo, out);
}

// round 6
// speedup vs baseline: 2.9896x; 1.2423x over previous
#include <cuda_runtime.h>
#include <cuda_bf16.h>
#include <cstdint>

#define B_  2
#define S_  2048
#define U_  1024
#define H_  16
#define DK_ 64
#define BS_ (B_ * S_)

// persistent split-bf16 scratch (allocation-free rule: __device__ globals)
__device__ __nv_bfloat16 in_q_hi[BS_ * U_], in_q_lo[BS_ * U_];
__device__ __nv_bfloat16 in_k_hi[BS_ * U_], in_k_lo[BS_ * U_];
__device__ __nv_bfloat16 in_v_hi[BS_ * U_], in_v_lo[BS_ * U_];
__device__ __nv_bfloat16 w_q_hi[U_ * U_], w_q_lo[U_ * U_];
__device__ __nv_bfloat16 w_k_hi[U_ * U_], w_k_lo[U_ * U_];
__device__ __nv_bfloat16 w_v_hi[U_ * U_], w_v_lo[U_ * U_];
__device__ __nv_bfloat16 w_o_hi[U_ * U_], w_o_lo[U_ * U_];
__device__ __nv_bfloat16 g_q_hi[BS_ * U_], g_q_lo[BS_ * U_];
__device__ __nv_bfloat16 g_k_hi[BS_ * U_], g_k_lo[BS_ * U_];
__device__ __nv_bfloat16 g_v_hi[BS_ * U_], g_v_lo[BS_ * U_];
__device__ __nv_bfloat16 g_att_hi[BS_ * U_], g_att_lo[BS_ * U_];

// ---------------------------------------------------------------------------
// helpers
// ---------------------------------------------------------------------------
__device__ __forceinline__ uint32_t smem_u32(const void* p) {
    uint32_t a;
    asm("{ .reg .u64 t; cvta.to.shared.u64 t, %1; cvt.u32.u64 %0, t; }" : "=r"(a) : "l"(p));
    return a;
}

#define LDSM_X4(r0, r1, r2, r3, addr)                                         \
    asm volatile("ldmatrix.sync.aligned.m8n8.x4.shared.b16 {%0,%1,%2,%3}, [%4];" \
        : "=r"(r0), "=r"(r1), "=r"(r2), "=r"(r3) : "r"(addr))

#define LDSM_X4_T(r0, r1, r2, r3, addr)                                       \
    asm volatile("ldmatrix.sync.aligned.m8n8.x4.trans.shared.b16 {%0,%1,%2,%3}, [%4];" \
        : "=r"(r0), "=r"(r1), "=r"(r2), "=r"(r3) : "r"(addr))

#define MMA_BF16(d, a, b0, b1)                                                \
    asm volatile("mma.sync.aligned.m16n8k16.row.col.f32.bf16.bf16.f32 "       \
        "{%0,%1,%2,%3},{%4,%5,%6,%7},{%8,%9},{%0,%1,%2,%3};"                  \
        : "+f"((d)[0]), "+f"((d)[1]), "+f"((d)[2]), "+f"((d)[3])              \
        : "r"((a)[0]), "r"((a)[1]), "r"((a)[2]), "r"((a)[3]), "r"(b0), "r"(b1))

#define CP_ASYNC16(saddr, gptr) \
    asm volatile("cp.async.cg.shared.global [%0], [%1], 16;" :: "r"(saddr), "l"(gptr) : "memory")
#define CP_COMMIT() asm volatile("cp.async.commit_group;" ::: "memory")
template <int N> __device__ __forceinline__ void cp_wait() {
    asm volatile("cp.async.wait_group %0;" :: "n"(N) : "memory");
}

__device__ __forceinline__ uint32_t pack_bf16(__nv_bfloat16 a, __nv_bfloat16 b) {
    uint32_t ua = *reinterpret_cast<unsigned short*>(&a);
    uint32_t ub = *reinterpret_cast<unsigned short*>(&b);
    return ua | (ub << 16);
}

__device__ __forceinline__ void cvt_split(const float4& f, uint2& hi, uint2& lo) {
    __nv_bfloat16 h0 = __float2bfloat16(f.x);
    __nv_bfloat16 h1 = __float2bfloat16(f.y);
    __nv_bfloat16 h2 = __float2bfloat16(f.z);
    __nv_bfloat16 h3 = __float2bfloat16(f.w);
    __nv_bfloat16 l0 = __float2bfloat16(f.x - __bfloat162float(h0));
    __nv_bfloat16 l1 = __float2bfloat16(f.y - __bfloat162float(h1));
    __nv_bfloat16 l2 = __float2bfloat16(f.z - __bfloat162float(h2));
    __nv_bfloat16 l3 = __float2bfloat16(f.w - __bfloat162float(h3));
    hi.x = pack_bf16(h0, h1); hi.y = pack_bf16(h2, h3);
    lo.x = pack_bf16(l0, l1); lo.y = pack_bf16(l2, l3);
}

__device__ __forceinline__ void pack_split2(float a, float b, uint32_t& hi, uint32_t& lo) {
    __nv_bfloat16 ha = __float2bfloat16(a), hb = __float2bfloat16(b);
    __nv_bfloat16 la = __float2bfloat16(a - __bfloat162float(ha));
    __nv_bfloat16 lb = __float2bfloat16(b - __bfloat162float(hb));
    hi = pack_bf16(ha, hb); lo = pack_bf16(la, lb);
}

// ---------------------------------------------------------------------------
// one-shot pre-pass: all 7 fp32 arrays -> (hi, lo) bf16.  blockIdx.y selects.
// ---------------------------------------------------------------------------
__global__ __launch_bounds__(256) void convert_all_kernel(
    const float* __restrict__ q, const float* __restrict__ k,
    const float* __restrict__ v, const float* __restrict__ wq,
    const float* __restrict__ wk, const float* __restrict__ wv,
    const float* __restrict__ wo,
    __nv_bfloat16* __restrict__ qh, __nv_bfloat16* __restrict__ ql,
    __nv_bfloat16* __restrict__ kh, __nv_bfloat16* __restrict__ kl,
    __nv_bfloat16* __restrict__ vh, __nv_bfloat16* __restrict__ vl,
    __nv_bfloat16* __restrict__ wqh, __nv_bfloat16* __restrict__ wql,
    __nv_bfloat16* __restrict__ wkh, __nv_bfloat16* __restrict__ wkl,
    __nv_bfloat16* __restrict__ wvh, __nv_bfloat16* __restrict__ wvl,
    __nv_bfloat16* __restrict__ woh, __nv_bfloat16* __restrict__ wol) {
    const float* src; __nv_bfloat16* hi; __nv_bfloat16* lo; int n4;
    switch (blockIdx.y) {
        case 0: src = q;  hi = qh;  lo = ql;  n4 = (BS_ * U_) / 4; break;
        case 1: src = k;  hi = kh;  lo = kl;  n4 = (BS_ * U_) / 4; break;
        case 2: src = v;  hi = vh;  lo = vl;  n4 = (BS_ * U_) / 4; break;
        case 3: src = wq; hi = wqh; lo = wql; n4 = (U_ * U_) / 4; break;
        case 4: src = wk; hi = wkh; lo = wkl; n4 = (U_ * U_) / 4; break;
        case 5: src = wv; hi = wvh; lo = wvl; n4 = (U_ * U_) / 4; break;
        default: src = wo; hi = woh; lo = wol; n4 = (U_ * U_) / 4; break;
    }
    for (int i = blockIdx.x * 256 + threadIdx.x; i < n4; i += 1024 * 256) {
        float4 f = ((const float4*)src)[i];
        uint2 h, l;
        cvt_split(f, h, l);
        ((uint2*)hi)[i] = h;
        ((uint2*)lo)[i] = l;
    }
}

// ---------------------------------------------------------------------------
// split-bf16 GEMM, cp.async 3-stage, single barrier per chunk.
// CTA 128(M) x 256(N), 512 threads, 16 warps (4M x 4N), warp tile 32x64.
// stage: Ahi@0 (10240), Alo@10240, Whi@20480 (20480), Wlo@40960
// ---------------------------------------------------------------------------
#define ROWB     80
#define ST_ALO   10240u
#define ST_WHI   20480u
#define ST_WLO   40960u
#define STAGE_B  61440
#define G_SMEM   (3 * STAGE_B)
#define NKC      (U_ / 32)

__device__ __forceinline__ void g_issue(uint32_t st,
                                        const __nv_bfloat16* __restrict__ Ah,
                                        const __nv_bfloat16* __restrict__ Al,
                                        const __nv_bfloat16* __restrict__ Wh,
                                        const __nv_bfloat16* __restrict__ Wl,
                                        int bm, int bn, int k0, int tid) {
    const int row = tid >> 2, seg = tid & 3;
    const uint32_t so = (uint32_t)(row * ROWB + seg * 16);
    const size_t ga  = (size_t)(bm + row) * U_ + k0 + seg * 8;
    const size_t gw0 = (size_t)(bn + row) * U_ + k0 + seg * 8;
    const size_t gw1 = (size_t)(bn + 128 + row) * U_ + k0 + seg * 8;
    CP_ASYNC16(st + so,                    Ah + ga);
    CP_ASYNC16(st + ST_ALO + so,           Al + ga);
    CP_ASYNC16(st + ST_WHI + so,           Wh + gw0);
    CP_ASYNC16(st + ST_WHI + 10240u + so,  Wh + gw1);
    CP_ASYNC16(st + ST_WLO + so,           Wl + gw0);
    CP_ASYNC16(st + ST_WLO + 10240u + so,  Wl + gw1);
}

template <bool SPLIT_OUT>
__device__ void gemm_bf_body(const __nv_bfloat16* __restrict__ Ah,
                             const __nv_bfloat16* __restrict__ Al,
                             const __nv_bfloat16* __restrict__ Wh,
                             const __nv_bfloat16* __restrict__ Wl,
                             const float* __restrict__ bias, float scale,
                             float* __restrict__ Cf,
                             __nv_bfloat16* __restrict__ Ch,
                             __nv_bfloat16* __restrict__ Cl) {
    extern __shared__ char smem[];
    const int tid  = threadIdx.x;
    const int lane = tid & 31;
    const int wid  = tid >> 5;
    const int wm   = wid >> 2;          // 0..3
    const int wn   = wid & 3;           // 0..3
    const int bm   = blockIdx.y * 128;
    const int bn   = blockIdx.x * 256;
    const uint32_t sbase = smem_u32(smem);

    float acc[2][8][4];
#pragma unroll
    for (int mf = 0; mf < 2; mf++)
#pragma unroll
        for (int nf = 0; nf < 8; nf++)
#pragma unroll
            for (int r = 0; r < 4; r++) acc[mf][nf][r] = 0.0f;

    const uint32_t a_row  = (uint32_t)(lane & 15);
    const uint32_t a_colh = (uint32_t)(((lane >> 4) & 1) * 16);
    const uint32_t b_nl   = (uint32_t)((lane & 7) + ((lane >> 4) & 1) * 8);
    const uint32_t b_ks   = (uint32_t)(((lane >> 3) & 1) * 16);

    g_issue(sbase, Ah, Al, Wh, Wl, bm, bn, 0, tid);  CP_COMMIT();
    g_issue(sbase + STAGE_B, Ah, Al, Wh, Wl, bm, bn, 32, tid);  CP_COMMIT();

    for (int c = 0; c < NKC; c++) {
        cp_wait<1>();
        __syncthreads();
        if (c + 2 < NKC)
            g_issue(sbase + (uint32_t)((c + 2) % 3) * STAGE_B, Ah, Al, Wh, Wl,
                    bm, bn, (c + 2) * 32, tid);
        CP_COMMIT();

        const uint32_t st = sbase + (uint32_t)(c % 3) * STAGE_B;
#pragma unroll
        for (int ko = 0; ko < 2; ko++) {
            uint32_t ah[2][4], al[2][4];
#pragma unroll
            for (int mf = 0; mf < 2; mf++) {
                uint32_t ad = st + (uint32_t)((wm * 32 + mf * 16 + a_row) * ROWB)
                                 + (uint32_t)(ko * 32) + a_colh;
                LDSM_X4(ah[mf][0], ah[mf][1], ah[mf][2], ah[mf][3], ad);
                LDSM_X4(al[mf][0], al[mf][1], al[mf][2], al[mf][3], ad + ST_ALO);
            }
            uint32_t bh[4][4], bl[4][4];
#pragma unroll
            for (int np = 0; np < 4; np++) {
                uint32_t bd = st + ST_WHI
                            + (uint32_t)((wn * 64 + np * 16 + b_nl) * ROWB)
                            + (uint32_t)(ko * 32) + b_ks;
                LDSM_X4(bh[np][0], bh[np][1], bh[np][2], bh[np][3], bd);
                LDSM_X4(bl[np][0], bl[np][1], bl[np][2], bl[np][3], bd + 20480u);
            }
#pragma unroll
            for (int mf = 0; mf < 2; mf++)
#pragma unroll
                for (int nf = 0; nf < 8; nf++) {
                    const uint32_t* bhp = &bh[nf >> 1][(nf & 1) * 2];
                    const uint32_t* blp = &bl[nf >> 1][(nf & 1) * 2];
                    MMA_BF16(acc[mf][nf], ah[mf], bhp[0], bhp[1]);
                    MMA_BF16(acc[mf][nf], ah[mf], blp[0], blp[1]);
                    MMA_BF16(acc[mf][nf], al[mf], bhp[0], bhp[1]);
                }
        }
    }

    const int tr = lane >> 2;
    const int tc = (lane & 3) * 2;
#pragma unroll
    for (int mf = 0; mf < 2; mf++) {
#pragma unroll
        for (int nf = 0; nf < 8; nf++) {
            int gr = bm + wm * 32 + mf * 16 + tr;
            int gc = bn + wn * 64 + nf * 8 + tc;
            float2 bv = *(const float2*)(bias + gc);
            if (SPLIT_OUT) {
                float a0 = (acc[mf][nf][0] + bv.x) * scale;
                float a1 = (acc[mf][nf][1] + bv.y) * scale;
                float a2 = (acc[mf][nf][2] + bv.x) * scale;
                float a3 = (acc[mf][nf][3] + bv.y) * scale;
                uint32_t h, l;
                pack_split2(a0, a1, h, l);
                *(uint32_t*)(Ch + (size_t)gr * U_ + gc) = h;
                *(uint32_t*)(Cl + (size_t)gr * U_ + gc) = l;
                pack_split2(a2, a3, h, l);
                *(uint32_t*)(Ch + (size_t)(gr + 8) * U_ + gc) = h;
                *(uint32_t*)(Cl + (size_t)(gr + 8) * U_ + gc) = l;
            } else {
                float2 o0 = make_float2(acc[mf][nf][0] + bv.x, acc[mf][nf][1] + bv.y);
                float2 o1 = make_float2(acc[mf][nf][2] + bv.x, acc[mf][nf][3] + bv.y);
                *(float2*)(Cf + (size_t)gr * U_ + gc)       = o0;
                *(float2*)(Cf + (size_t)(gr + 8) * U_ + gc) = o1;
            }
        }
    }
}

__global__ __launch_bounds__(512, 1) void gemm_bf_qkv_b(
    const float* __restrict__ bq, const float* __restrict__ bk,
    const float* __restrict__ bv) {
    if (blockIdx.z == 0)
        gemm_bf_body<true>(in_q_hi, in_q_lo, w_q_hi, w_q_lo, bq, 0.125f,
                           nullptr, g_q_hi, g_q_lo);
    else if (blockIdx.z == 1)
        gemm_bf_body<true>(in_k_hi, in_k_lo, w_k_hi, w_k_lo, bk, 1.0f,
                           nullptr, g_k_hi, g_k_lo);
    else
        gemm_bf_body<true>(in_v_hi, in_v_lo, w_v_hi, w_v_lo, bv, 1.0f,
                           nullptr, g_v_hi, g_v_lo);
}

__global__ __launch_bounds__(512, 1) void gemm_bf_out(const float* __restrict__ bo,
                                                      float* __restrict__ out) {
    gemm_bf_body<false>(g_att_hi, g_att_lo, w_o_hi, w_o_lo, bo, 1.0f,
                        out, nullptr, nullptr);
}

// ---------------------------------------------------------------------------
// Flash attention, split-bf16 mma.sync, cp.async double-buffered K/V,
// single barrier per kv tile.
// ---------------------------------------------------------------------------
#define AROWB    144
#define AQ_LO_O  18432u
#define AST0     36864u
#define ASTAGE_B 36864u
#define ATT_SMEM 110592

__device__ __forceinline__ void kv_issue(uint32_t buf,
                                         const __nv_bfloat16* __restrict__ Kh,
                                         const __nv_bfloat16* __restrict__ Kl,
                                         const __nv_bfloat16* __restrict__ Vh,
                                         const __nv_bfloat16* __restrict__ Vl,
                                         int kbase, int tid) {
#pragma unroll
    for (int i = 0; i < 2; i++) {
        int id  = tid * 2 + i;
        int row = id >> 3, seg = id & 7;
        uint32_t so = (uint32_t)(row * AROWB + seg * 16);
        size_t go = (size_t)(kbase + row) * U_ + seg * 8;
        CP_ASYNC16(buf + so,          Kh + go);
        CP_ASYNC16(buf + 9216u + so,  Kl + go);
        CP_ASYNC16(buf + 18432u + so, Vh + go);
        CP_ASYNC16(buf + 27648u + so, Vl + go);
    }
}

__global__ __launch_bounds__(256, 1) void flash_attn_mma() {
    extern __shared__ char smem[];
    const uint32_t sb = smem_u32(smem);
    const int tid  = threadIdx.x;
    const int lane = tid & 31;
    const int wid  = tid >> 5;
    const int qt   = (int)gridDim.x - 1 - (int)blockIdx.x;   // big tiles first
    const int h    = blockIdx.y;
    const int b    = blockIdx.z;
    const int qbase = qt * 128;

    const size_t head_off = (size_t)b * S_ * U_ + h * DK_;
    const __nv_bfloat16* Qh = g_q_hi + head_off + (size_t)qbase * U_;
    const __nv_bfloat16* Ql = g_q_lo + head_off + (size_t)qbase * U_;
    const __nv_bfloat16* Kh = g_k_hi + head_off;
    const __nv_bfloat16* Kl = g_k_lo + head_off;
    const __nv_bfloat16* Vh = g_v_hi + head_off;
    const __nv_bfloat16* Vl = g_v_lo + head_off;

    // Q tile cp.async (one-time)
#pragma unroll
    for (int i = 0; i < 4; i++) {
        int id  = tid * 4 + i;
        int row = id >> 3, seg = id & 7;
        uint32_t so = (uint32_t)(row * AROWB + seg * 16);
        size_t go = (size_t)row * U_ + seg * 8;
        CP_ASYNC16(sb + so,           Qh + go);
        CP_ASYNC16(sb + AQ_LO_O + so, Ql + go);
    }
    CP_COMMIT();
    kv_issue(sb + AST0, Kh, Kl, Vh, Vl, 0, tid);
    CP_COMMIT();

    const uint32_t a_row  = (uint32_t)(lane & 15);
    const uint32_t a_colh = (uint32_t)(((lane >> 4) & 1) * 16);
    const uint32_t b_nl   = (uint32_t)((lane & 7) + ((lane >> 4) & 1) * 8);
    const uint32_t b_ks   = (uint32_t)(((lane >> 3) & 1) * 16);
    const uint32_t v_row  = (uint32_t)(((lane >> 3) & 1) * 8 + (lane & 7));
    const uint32_t v_colh = (uint32_t)(((lane >> 4) & 1) * 16);

    // hoist Q fragments (Q group done; kv group may still be pending)
    cp_wait<1>();
    __syncthreads();
    uint32_t qh[4][4], ql[4][4];
#pragma unroll
    for (int ko = 0; ko < 4; ko++) {
        uint32_t ad = sb + (uint32_t)((wid * 16 + a_row) * AROWB)
                    + (uint32_t)(ko * 32) + a_colh;
        LDSM_X4(qh[ko][0], qh[ko][1], qh[ko][2], qh[ko][3], ad);
        LDSM_X4(ql[ko][0], ql[ko][1], ql[ko][2], ql[ko][3], ad + AQ_LO_O);
    }

    float m0 = -1e30f, m1 = -1e30f, l0 = 0.0f, l1 = 0.0f;
    float oacc[8][4];
#pragma unroll
    for (int nf = 0; nf < 8; nf++)
#pragma unroll
        for (int r = 0; r < 4; r++) oacc[nf][r] = 0.0f;

    const int njt = 2 * qt + 2;
    for (int jt = 0; jt < njt; jt++) {
        const int kbase = jt * 64;
        cp_wait<0>();
        __syncthreads();
        if (jt + 1 < njt)
            kv_issue(sb + AST0 + (uint32_t)((jt + 1) & 1) * ASTAGE_B,
                     Kh, Kl, Vh, Vl, (jt + 1) * 64, tid);
        CP_COMMIT();

        const uint32_t st = sb + AST0 + (uint32_t)(jt & 1) * ASTAGE_B;

        // S = Q K^T
        float sacc[8][4];
#pragma unroll
        for (int j = 0; j < 8; j++)
#pragma unroll
            for (int r = 0; r < 4; r++) sacc[j][r] = 0.0f;

#pragma unroll
        for (int ko = 0; ko < 4; ko++) {
#pragma unroll
            for (int np = 0; np < 4; np++) {
                uint32_t kh[4], kl[4];
                uint32_t bd = st + (uint32_t)((np * 16 + b_nl) * AROWB)
                            + (uint32_t)(ko * 32) + b_ks;
                LDSM_X4(kh[0], kh[1], kh[2], kh[3], bd);
                LDSM_X4(kl[0], kl[1], kl[2], kl[3], bd + 9216u);
#pragma unroll
                for (int half = 0; half < 2; half++) {
                    float* d = sacc[2 * np + half];
                    const uint32_t* bh = &kh[half * 2];
                    const uint32_t* bl = &kl[half * 2];
                    MMA_BF16(d, qh[ko], bh[0], bh[1]);
                    MMA_BF16(d, qh[ko], bl[0], bl[1]);
                    MMA_BF16(d, ql[ko], bh[0], bh[1]);
                }
            }
        }

        // causal mask on diagonal-overlapping tiles
        if (jt >= 2 * qt) {
            const int row0 = qbase + wid * 16 + (lane >> 2);
            const int row1 = row0 + 8;
#pragma unroll
            for (int j = 0; j < 8; j++) {
                int col = kbase + 8 * j + 2 * (lane & 3);
                if (col > row0)     sacc[j][0] = -1e9f;
                if (col + 1 > row0) sacc[j][1] = -1e9f;
                if (col > row1)     sacc[j][2] = -1e9f;
                if (col + 1 > row1) sacc[j][3] = -1e9f;
            }
        }

        // online softmax (in-warp quad reductions)
        float rm0 = -1e30f, rm1 = -1e30f;
#pragma unroll
        for (int j = 0; j < 8; j++) {
            rm0 = fmaxf(rm0, fmaxf(sacc[j][0], sacc[j][1]));
            rm1 = fmaxf(rm1, fmaxf(sacc[j][2], sacc[j][3]));
        }
        rm0 = fmaxf(rm0, __shfl_xor_sync(0xffffffffu, rm0, 1));
        rm0 = fmaxf(rm0, __shfl_xor_sync(0xffffffffu, rm0, 2));
        rm1 = fmaxf(rm1, __shfl_xor_sync(0xffffffffu, rm1, 1));
        rm1 = fmaxf(rm1, __shfl_xor_sync(0xffffffffu, rm1, 2));
        float mn0 = fmaxf(m0, rm0), mn1 = fmaxf(m1, rm1);
        float corr0 = __expf(m0 - mn0), corr1 = __expf(m1 - mn1);
        m0 = mn0; m1 = mn1;
        float rs0 = 0.0f, rs1 = 0.0f;
#pragma unroll
        for (int j = 0; j < 8; j++) {
            float p0 = __expf(sacc[j][0] - mn0);
            float p1 = __expf(sacc[j][1] - mn0);
            float p2 = __expf(sacc[j][2] - mn1);
            float p3 = __expf(sacc[j][3] - mn1);
            sacc[j][0] = p0; sacc[j][1] = p1; sacc[j][2] = p2; sacc[j][3] = p3;
            rs0 += p0 + p1; rs1 += p2 + p3;
        }
        rs0 += __shfl_xor_sync(0xffffffffu, rs0, 1);
        rs0 += __shfl_xor_sync(0xffffffffu, rs0, 2);
        rs1 += __shfl_xor_sync(0xffffffffu, rs1, 1);
        rs1 += __shfl_xor_sync(0xffffffffu, rs1, 2);
        l0 = l0 * corr0 + rs0;
        l1 = l1 * corr1 + rs1;
#pragma unroll
        for (int nf = 0; nf < 8; nf++) {
            oacc[nf][0] *= corr0; oacc[nf][1] *= corr0;
            oacc[nf][2] *= corr1; oacc[nf][3] *= corr1;
        }

        // O += P V
#pragma unroll
        for (int t = 0; t < 4; t++) {
            uint32_t ph[4], pl[4];
            pack_split2(sacc[2 * t][0],     sacc[2 * t][1],     ph[0], pl[0]);
            pack_split2(sacc[2 * t][2],     sacc[2 * t][3],     ph[1], pl[1]);
            pack_split2(sacc[2 * t + 1][0], sacc[2 * t + 1][1], ph[2], pl[2]);
            pack_split2(sacc[2 * t + 1][2], sacc[2 * t + 1][3], ph[3], pl[3]);
            uint32_t vh[4][4], vl[4][4];
#pragma unroll
            for (int g = 0; g < 4; g++) {
                uint32_t va = st + 18432u + (uint32_t)((t * 16 + v_row) * AROWB)
                            + v_colh + (uint32_t)(g * 32);
                LDSM_X4_T(vh[g][0], vh[g][1], vh[g][2], vh[g][3], va);
                LDSM_X4_T(vl[g][0], vl[g][1], vl[g][2], vl[g][3], va + 9216u);
            }
#pragma unroll
            for (int nf = 0; nf < 8; nf++) {
                const int g = nf >> 1;
                const uint32_t* bh = &vh[g][(nf & 1) * 2];
                const uint32_t* bl = &vl[g][(nf & 1) * 2];
                MMA_BF16(oacc[nf], ph, bh[0], bh[1]);
                MMA_BF16(oacc[nf], pl, bh[0], bh[1]);
                MMA_BF16(oacc[nf], ph, bl[0], bl[1]);
            }
        }
    }

    // epilogue: normalize, split, write g_att hi/lo
    const float inv0 = 1.0f / l0, inv1 = 1.0f / l1;
    const int row0 = qbase + wid * 16 + (lane >> 2);
    const size_t obase = (size_t)b * S_ * U_ + (size_t)row0 * U_ + h * DK_ + 2 * (lane & 3);
#pragma unroll
    for (int nf = 0; nf < 8; nf++) {
        uint32_t h32, l32;
        pack_split2(oacc[nf][0] * inv0, oacc[nf][1] * inv0, h32, l32);
        *(uint32_t*)(g_att_hi + obase + 8 * nf) = h32;
        *(uint32_t*)(g_att_lo + obase + 8 * nf) = l32;
        pack_split2(oacc[nf][2] * inv1, oacc[nf][3] * inv1, h32, l32);
        *(uint32_t*)(g_att_hi + obase + 8 * (size_t)U_ + 8 * nf) = h32;
        *(uint32_t*)(g_att_lo + obase + 8 * (size_t)U_ + 8 * nf) = l32;
    }
}

// ---------------------------------------------------------------------------
extern "C" void kernel_launch(void* const* d_in, const int* in_sizes, int n_in,
                              void* d_out, int out_size) {
    const float* query = (const float*)d_in[0];
    const float* key   = (const float*)d_in[1];
    const float* value = (const float*)d_in[2];
    const float* Wq = (const float*)d_in[4];
    const float* bq = (const float*)d_in[5];
    const float* Wk = (const float*)d_in[6];
    const float* bk = (const float*)d_in[7];
    const float* Wv = (const float*)d_in[8];
    const float* bv = (const float*)d_in[9];
    const float* Wo = (const float*)d_in[10];
    const float* bo = (const float*)d_in[11];
    float* out = (float*)d_out;

    cudaFuncSetAttribute(gemm_bf_qkv_b, cudaFuncAttributeMaxDynamicSharedMemorySize, G_SMEM);
    cudaFuncSetAttribute(gemm_bf_out, cudaFuncAttributeMaxDynamicSharedMemorySize, G_SMEM);
    cudaFuncSetAttribute(flash_attn_mma, cudaFuncAttributeMaxDynamicSharedMemorySize, ATT_SMEM);

    static __nv_bfloat16 *p_iqh = nullptr, *p_iql, *p_ikh, *p_ikl, *p_ivh, *p_ivl;
    static __nv_bfloat16 *p_wqh, *p_wql, *p_wkh, *p_wkl, *p_wvh, *p_wvl, *p_woh, *p_wol;
    if (!p_iqh) {
        cudaGetSymbolAddress((void**)&p_iqh, in_q_hi);
        cudaGetSymbolAddress((void**)&p_iql, in_q_lo);
        cudaGetSymbolAddress((void**)&p_ikh, in_k_hi);
        cudaGetSymbolAddress((void**)&p_ikl, in_k_lo);
        cudaGetSymbolAddress((void**)&p_ivh, in_v_hi);
        cudaGetSymbolAddress((void**)&p_ivl, in_v_lo);
        cudaGetSymbolAddress((void**)&p_wqh, w_q_hi);
        cudaGetSymbolAddress((void**)&p_wql, w_q_lo);
        cudaGetSymbolAddress((void**)&p_wkh, w_k_hi);
        cudaGetSymbolAddress((void**)&p_wkl, w_k_lo);
        cudaGetSymbolAddress((void**)&p_wvh, w_v_hi);
        cudaGetSymbolAddress((void**)&p_wvl, w_v_lo);
        cudaGetSymbolAddress((void**)&p_woh, w_o_hi);
        cudaGetSymbolAddress((void**)&p_wol, w_o_lo);
    }

    dim3 gc(1024, 7, 1);
    convert_all_kernel<<<gc, 256>>>(query, key, value, Wq, Wk, Wv, Wo,
                                    p_iqh, p_iql, p_ikh, p_ikl, p_ivh, p_ivl,
                                    p_wqh, p_wql, p_wkh, p_wkl, p_wvh, p_wvl,
                                    p_woh, p_wol);

    dim3 gq(U_ / 256, BS_ / 128, 3);
    gemm_bf_qkv_b<<<gq, 512, G_SMEM>>>(bq, bk, bv);

    dim3 ga(S_ / 128, H_, B_);
    flash_attn_mma<<<ga, 256, ATT_SMEM>>>();

    dim3 go(U_ / 256, BS_ / 128, 1);
    gemm_bf_out<<<go, 512, G_SMEM>>>(bo, out);
}